// round 12
// baseline (speedup 1.0000x reference)
#include <cuda_runtime.h>
#include <cuda_fp16.h>
#include <cuda_bf16.h>
#include <cstdint>

#define NATTRS 250
#define NOBJS  400
#define NNODES 650
#define NEDGES 100000
#define DIN    512
#define DHID   4096
#define DNODE  512
#define FEATD  2048
#define EMBD   800
#define BATCH  256
#define P1D    1200
#define NPAIRS (NATTRS * NOBJS)
#define LNEPS  1e-5f

// ---------------- scratch (single __device__ global; no allocs) ----------------
#define OFF_ADJ    0ull
#define OFF_MEAN1  (OFF_ADJ   + (size_t)NNODES * NNODES)
#define OFF_H      (OFF_MEAN1 + (size_t)NNODES * DIN)
#define OFF_T2     (OFF_H     + (size_t)NNODES * DHID)
#define OFF_ON     (OFF_T2    + (size_t)NNODES * 1024)
#define OFF_PP     (OFF_ON    + (size_t)NNODES * DNODE)
#define OFF_Q      (OFF_PP    + (size_t)NNODES * P1D)
#define OFF_I1     (OFF_Q     + (size_t)NPAIRS * EMBD)
#define OFF_I2     (OFF_I1    + (size_t)BATCH * 768)
#define OFF_I3     (OFF_I2    + (size_t)BATCH * 1024)
#define SCRATCH_ELEMS (OFF_I3 + (size_t)BATCH * EMBD)

__device__ float g_scratch[SCRATCH_ELEMS];

// split-bf16 weight buffers
__device__ uint16_t g_w1c_hi[(size_t)DHID * 1024];
__device__ uint16_t g_w1c_lo[(size_t)DHID * 1024];
__device__ uint16_t g_w2c_hi[(size_t)1024 * DHID];
__device__ uint16_t g_w2c_lo[(size_t)1024 * DHID];
__device__ uint16_t g_wp1_hi[(size_t)P1D * 1024];
__device__ uint16_t g_wp1_lo[(size_t)P1D * 1024];
__device__ uint16_t g_wi1_hi[(size_t)768 * FEATD];
__device__ uint16_t g_wi1_lo[(size_t)768 * FEATD];
__device__ uint16_t g_wi2_hi[(size_t)1000 * 768];
__device__ uint16_t g_wi2_lo[(size_t)1000 * 768];
__device__ uint16_t g_wi3_hi[(size_t)EMBD * 1024];
__device__ uint16_t g_wi3_lo[(size_t)EMBD * 1024];
// fp16 buffers
__device__ uint16_t g_wp2h[(size_t)EMBD * P1D];
__device__ uint16_t g_ph[(size_t)NPAIRS * EMBD];
__device__ uint16_t g_pah[(size_t)NATTRS * P1D];
__device__ uint16_t g_poh[(size_t)NOBJS * P1D];

// ---------------- small kernels ----------------
__global__ void zero_kernel(float* p, int n) {
    int i = blockIdx.x * blockDim.x + threadIdx.x;
    if (i < n) p[i] = 0.0f;
}

__global__ void edge_count_kernel(const int* __restrict__ src,
                                  const int* __restrict__ dst,
                                  float* __restrict__ adj) {
    int e = blockIdx.x * blockDim.x + threadIdx.x;
    if (e < NEDGES) atomicAdd(&adj[(size_t)dst[e] * NNODES + src[e]], 1.0f);
}

__global__ void row_norm_kernel(float* __restrict__ adj) {
    __shared__ float sbuf[32];
    int r = blockIdx.x;
    int tid = threadIdx.x;
    float s = 0.0f;
    float* row = adj + (size_t)r * NNODES;
    for (int c = tid; c < NNODES; c += blockDim.x) s += row[c];
    for (int o = 16; o > 0; o >>= 1) s += __shfl_down_sync(0xffffffffu, s, o);
    if ((tid & 31) == 0) sbuf[tid >> 5] = s;
    __syncthreads();
    int nw = blockDim.x >> 5;
    if (tid < 32) {
        s = (tid < nw) ? sbuf[tid] : 0.0f;
        for (int o = 16; o > 0; o >>= 1) s += __shfl_down_sync(0xffffffffu, s, o);
        if (tid == 0) sbuf[0] = s;
    }
    __syncthreads();
    float inv = 1.0f / fmaxf(sbuf[0], 1.0f);
    for (int c = tid; c < NNODES; c += blockDim.x) row[c] *= inv;
}

// vectorized split-concat (x8): out row k<K1 from X1, else X2; pad 0
__global__ void splitcat8_kernel(const float* __restrict__ X1, int K1,
                                 const float* __restrict__ X2, int K2,
                                 uint16_t* __restrict__ hi, uint16_t* __restrict__ lo,
                                 int ldo, int Nrows) {
    int g = blockIdx.x * blockDim.x + threadIdx.x;
    int total = Nrows * ldo / 8;
    if (g >= total) return;
    int base = g * 8;
    int n = base / ldo, k = base - n * ldo;
    float v[8];
    if (k + 8 <= K1) {
        const float4* s = (const float4*)(X1 + (size_t)n * K1 + k);
        float4 a = s[0], b = s[1];
        v[0]=a.x; v[1]=a.y; v[2]=a.z; v[3]=a.w; v[4]=b.x; v[5]=b.y; v[6]=b.z; v[7]=b.w;
    } else if (k >= K1 && k + 8 <= K1 + K2) {
        const float4* s = (const float4*)(X2 + (size_t)n * K2 + (k - K1));
        float4 a = s[0], b = s[1];
        v[0]=a.x; v[1]=a.y; v[2]=a.z; v[3]=a.w; v[4]=b.x; v[5]=b.y; v[6]=b.z; v[7]=b.w;
    } else {
#pragma unroll
        for (int q = 0; q < 8; q++) {
            int kk = k + q;
            v[q] = (kk < K1) ? X1[(size_t)n * K1 + kk]
                 : (kk < K1 + K2 ? X2[(size_t)n * K2 + (kk - K1)] : 0.0f);
        }
    }
    union { uint16_t b[8]; uint4 u; } Uh, Ul;
#pragma unroll
    for (int q = 0; q < 8; q++) {
        __nv_bfloat16 h = __float2bfloat16(v[q]);
        Uh.b[q] = __bfloat16_as_ushort(h);
        Ul.b[q] = __bfloat16_as_ushort(__float2bfloat16(v[q] - __bfloat162float(h)));
    }
    *(uint4*)(hi + base) = Uh.u;
    *(uint4*)(lo + base) = Ul.u;
}

__global__ void tohalf8_kernel(const float* __restrict__ x,
                               uint16_t* __restrict__ y, int n8) {
    int g = blockIdx.x * blockDim.x + threadIdx.x;
    if (g >= n8) return;
    const float4* s = (const float4*)(x + g * 8);
    float4 a = s[0], b = s[1];
    union { uint16_t h[8]; uint4 u; } U;
    U.h[0] = __half_as_ushort(__float2half_rn(a.x));
    U.h[1] = __half_as_ushort(__float2half_rn(a.y));
    U.h[2] = __half_as_ushort(__float2half_rn(a.z));
    U.h[3] = __half_as_ushort(__float2half_rn(a.w));
    U.h[4] = __half_as_ushort(__float2half_rn(b.x));
    U.h[5] = __half_as_ushort(__float2half_rn(b.y));
    U.h[6] = __half_as_ushort(__float2half_rn(b.z));
    U.h[7] = __half_as_ushort(__float2half_rn(b.w));
    *(uint4*)(y + g * 8) = U.u;
}

// PP [650x1200] -> fp16 tables: pah = fp16(PP[:250] + bp1), poh = fp16(PP[250:])
__global__ void pp2half_kernel(const float* __restrict__ PP,
                               const float* __restrict__ bp1,
                               uint16_t* __restrict__ pah,
                               uint16_t* __restrict__ poh) {
    int i = blockIdx.x * blockDim.x + threadIdx.x;
    if (i >= NNODES * P1D) return;
    int r = i / P1D, k = i - r * P1D;
    float v = PP[i];
    if (r < NATTRS) {
        pah[(size_t)r * P1D + k] = __half_as_ushort(__float2half_rn(v + bp1[k]));
    } else {
        poh[(size_t)(r - NATTRS) * P1D + k] = __half_as_ushort(__float2half_rn(v));
    }
}

// in-place LayerNorm (fp32)
__global__ void ln_kernel(float* __restrict__ X,
                          const float* __restrict__ g,
                          const float* __restrict__ b, int D) {
    __shared__ float sA[32], sB[32];
    int r = blockIdx.x;
    int tid = threadIdx.x;
    float* x = X + (size_t)r * D;
    float s = 0.0f, s2 = 0.0f;
    for (int d = tid; d < D; d += blockDim.x) { float v = x[d]; s += v; s2 += v * v; }
    for (int o = 16; o > 0; o >>= 1) {
        s += __shfl_down_sync(0xffffffffu, s, o);
        s2 += __shfl_down_sync(0xffffffffu, s2, o);
    }
    if ((tid & 31) == 0) { sA[tid >> 5] = s; sB[tid >> 5] = s2; }
    __syncthreads();
    int nw = blockDim.x >> 5;
    if (tid < 32) {
        s = (tid < nw) ? sA[tid] : 0.0f;
        s2 = (tid < nw) ? sB[tid] : 0.0f;
        for (int o = 16; o > 0; o >>= 1) {
            s += __shfl_down_sync(0xffffffffu, s, o);
            s2 += __shfl_down_sync(0xffffffffu, s2, o);
        }
        if (tid == 0) { sA[0] = s; sB[0] = s2; }
    }
    __syncthreads();
    float invD = 1.0f / (float)D;
    float m = sA[0] * invD;
    float var = fmaxf(sB[0] * invD - m * m, 0.0f);
    float inv = rsqrtf(var + LNEPS);
    for (int d = tid; d < D; d += blockDim.x)
        x[d] = (x[d] - m) * inv * g[d] + b[d];
}

// LayerNorm of Q rows -> fp16 P
__global__ void ln_half_kernel(const float* __restrict__ Q,
                               const float* __restrict__ g,
                               const float* __restrict__ b,
                               uint16_t* __restrict__ Ph) {
    __shared__ float sA[32], sB[32];
    int r = blockIdx.x;
    int tid = threadIdx.x;
    const float* x = Q + (size_t)r * EMBD;
    float s = 0.0f, s2 = 0.0f;
    for (int d = tid; d < EMBD; d += blockDim.x) { float v = x[d]; s += v; s2 += v * v; }
    for (int o = 16; o > 0; o >>= 1) {
        s += __shfl_down_sync(0xffffffffu, s, o);
        s2 += __shfl_down_sync(0xffffffffu, s2, o);
    }
    if ((tid & 31) == 0) { sA[tid >> 5] = s; sB[tid >> 5] = s2; }
    __syncthreads();
    int nw = blockDim.x >> 5;
    if (tid < 32) {
        s = (tid < nw) ? sA[tid] : 0.0f;
        s2 = (tid < nw) ? sB[tid] : 0.0f;
        for (int o = 16; o > 0; o >>= 1) {
            s += __shfl_down_sync(0xffffffffu, s, o);
            s2 += __shfl_down_sync(0xffffffffu, s2, o);
        }
        if (tid == 0) { sA[0] = s; sB[0] = s2; }
    }
    __syncthreads();
    float invD = 1.0f / (float)EMBD;
    float m = sA[0] * invD;
    float var = fmaxf(sB[0] * invD - m * m, 0.0f);
    float inv = rsqrtf(var + LNEPS);
    for (int d = tid; d < EMBD; d += blockDim.x) {
        float p = (x[d] - m) * inv * g[d] + b[d];
        Ph[(size_t)r * EMBD + d] = __half_as_ushort(__float2half_rn(p));
    }
}

// ---------------- small fp32 NN gemm (64x64 tiles) ----------------
__global__ __launch_bounds__(256)
void nn_small_kernel(const float* __restrict__ A, int lda,
                     const float* __restrict__ B, int ldb,
                     const float* __restrict__ bias,
                     const float* __restrict__ extra, int lde,
                     float* __restrict__ C, int ldc,
                     int M, int N, int K) {
    __shared__ float As[16][68];
    __shared__ float Bs[16][68];
    int tid = threadIdx.x;
    int bm = blockIdx.y * 64, bn = blockIdx.x * 64;
    int tx = tid & 15, ty = tid >> 4;
    float acc[4][4];
#pragma unroll
    for (int i = 0; i < 4; i++)
#pragma unroll
        for (int j = 0; j < 4; j++) acc[i][j] = 0.0f;
    for (int k0 = 0; k0 < K; k0 += 16) {
        for (int e = tid; e < 1024; e += 256) {
            int row = e & 63, kk = e >> 6;
            int gm = bm + row, gk = k0 + kk, gn = bn + row;
            As[kk][row] = (gm < M && gk < K) ? A[(size_t)gm * lda + gk] : 0.0f;
            Bs[kk][row] = (gn < N && gk < K) ? B[(size_t)gk * ldb + gn] : 0.0f;
        }
        __syncthreads();
#pragma unroll
        for (int kk = 0; kk < 16; kk++) {
            float a[4], b[4];
#pragma unroll
            for (int i = 0; i < 4; i++) a[i] = As[kk][ty * 4 + i];
#pragma unroll
            for (int j = 0; j < 4; j++) b[j] = Bs[kk][tx * 4 + j];
#pragma unroll
            for (int i = 0; i < 4; i++)
#pragma unroll
                for (int j = 0; j < 4; j++) acc[i][j] += a[i] * b[j];
        }
        __syncthreads();
    }
#pragma unroll
    for (int i = 0; i < 4; i++) {
        int m = bm + ty * 4 + i;
        if (m >= M) continue;
#pragma unroll
        for (int j = 0; j < 4; j++) {
            int n = bn + tx * 4 + j;
            if (n >= N) continue;
            float v = acc[i][j];
            if (bias) v += bias[n];
            if (extra) v += extra[(size_t)m * lde + n];
            C[(size_t)m * ldc + n] = v;
        }
    }
}

// ================= generalized tensor-core GEMM =================
// C[M,NB] = A[M,K] @ B[NB,K]^T  (+bias), optional relu.
// SPLIT=1: 3-term split-bf16 (KS=32). SPLIT=0: single-term fp16 (KS=32/64).
// AMODE 0: A = A1 (fp32, lda1)
// AMODE 1: A[r,k] = relu_fp16(H1[r/NOBJS,k] + H2[r%NOBJS,k])  (fp16 tables; SPLIT=0)
// AMODE 2: A[r,k] = k<K1 ? A1[r,k] : A2[r,k-K1]
// AMODE 3: A[r,k] = r<NATTRS ? (k<K1 ? A1[r,k] : 0) : (k>=K1 ? A1[r,k-K1] : 0)
// CTA tile: 128(M) x NT_(N), K-stage KS_ (KS_/16 sub-k16).

__device__ __forceinline__ uint32_t smem_u32(const void* p) {
    return (uint32_t)__cvta_generic_to_shared(p);
}
__device__ __forceinline__ void ldmA4(uint32_t r[4], uint32_t addr) {
    asm volatile("ldmatrix.sync.aligned.m8n8.x4.shared.b16 {%0,%1,%2,%3},[%4];\n"
                 : "=r"(r[0]), "=r"(r[1]), "=r"(r[2]), "=r"(r[3]) : "r"(addr));
}
__device__ __forceinline__ void ldmB2(uint32_t r[2], uint32_t addr) {
    asm volatile("ldmatrix.sync.aligned.m8n8.x2.shared.b16 {%0,%1},[%2];\n"
                 : "=r"(r[0]), "=r"(r[1]) : "r"(addr));
}
// paired B load: 2 n-groups (16 rows) x 16 k-cols in one ldmatrix.x4
__device__ __forceinline__ void ldmB4(uint32_t r0[2], uint32_t r1[2], uint32_t addr) {
    asm volatile("ldmatrix.sync.aligned.m8n8.x4.shared.b16 {%0,%1,%2,%3},[%4];\n"
                 : "=r"(r0[0]), "=r"(r0[1]), "=r"(r1[0]), "=r"(r1[1]) : "r"(addr));
}
__device__ __forceinline__ void mma_f16(float d[4], const uint32_t a[4],
                                        const uint32_t b[2]) {
    asm volatile(
        "mma.sync.aligned.m16n8k16.row.col.f32.f16.f16.f32 "
        "{%0,%1,%2,%3},{%4,%5,%6,%7},{%8,%9},{%0,%1,%2,%3};\n"
        : "+f"(d[0]), "+f"(d[1]), "+f"(d[2]), "+f"(d[3])
        : "r"(a[0]), "r"(a[1]), "r"(a[2]), "r"(a[3]), "r"(b[0]), "r"(b[1]));
}
__device__ __forceinline__ void mma_bf16(float d[4], const uint32_t a[4],
                                         const uint32_t b[2]) {
    asm volatile(
        "mma.sync.aligned.m16n8k16.row.col.f32.bf16.bf16.f32 "
        "{%0,%1,%2,%3},{%4,%5,%6,%7},{%8,%9},{%0,%1,%2,%3};\n"
        : "+f"(d[0]), "+f"(d[1]), "+f"(d[2]), "+f"(d[3])
        : "r"(a[0]), "r"(a[1]), "r"(a[2]), "r"(a[3]), "r"(b[0]), "r"(b[1]));
}
__device__ __forceinline__ void cp16(uint32_t dst, const void* src) {
    asm volatile("cp.async.cg.shared.global [%0], [%1], 16;\n" :: "r"(dst), "l"(src));
}
__device__ __forceinline__ void cp_commit() { asm volatile("cp.async.commit_group;\n"); }
__device__ __forceinline__ void cp_wait0()  { asm volatile("cp.async.wait_group 0;\n"); }

__device__ __forceinline__ uint32_t h2addrelu(uint32_t a, uint32_t b) {
    __half2 ha = *(__half2*)&a;
    __half2 hb = *(__half2*)&b;
    __half2 r = __hmax2(__hadd2(ha, hb), __float2half2_rn(0.0f));
    return *(uint32_t*)&r;
}
__device__ __forceinline__ uint4 h2addrelu4(uint4 a, uint4 b) {
    uint4 r;
    r.x = h2addrelu(a.x, b.x); r.y = h2addrelu(a.y, b.y);
    r.z = h2addrelu(a.z, b.z); r.w = h2addrelu(a.w, b.w);
    return r;
}

template <int AMODE, int SPLIT, int RELU, int NT_, int KS_>
__global__ __launch_bounds__(256)
void mma2_kernel(const float* __restrict__ A1, int lda1,
                 const float* __restrict__ A2, int lda2, int K1,
                 const uint16_t* __restrict__ H1,
                 const uint16_t* __restrict__ H2, int ldh,
                 const uint16_t* __restrict__ Bhi,
                 const uint16_t* __restrict__ Blo, int ldb,
                 float* __restrict__ C, int ldc,
                 int M, int NB, int K,
                 const float* __restrict__ bias,
                 const float* __restrict__ bias1) {
    constexpr int NI   = NT_ / 32;
    constexpr int RB   = (KS_ + 8) * 2;     // bytes per smem row (8-half pad)
    constexpr int ASZ  = 128 * RB;
    constexpr int BSZ  = NT_ * RB;
    constexpr int NPLA = SPLIT ? 2 : 1;
    constexpr int STRIDE = NPLA * (ASZ + BSZ);
    constexpr int AhiO = 0;
    constexpr int AloO = ASZ;
    constexpr int BhiO = NPLA * ASZ;
    constexpr int BloO = NPLA * ASZ + BSZ;
    constexpr int NSUB = KS_ / 16;          // k16 sub-steps per stage
    constexpr int GH   = KS_ / 16;          // 8-half groups per thread (A covers KS_/2)

    extern __shared__ char smem[];
    const uint32_t sb = smem_u32(smem);
    const int tid = threadIdx.x;
    const int warp = tid >> 5;
    const int lane = tid & 31;
    const int bm = blockIdx.y * 128;
    const int bn = blockIdx.x * NT_;
    const int wm = warp & 1;
    const int wn = warp >> 1;

    const int ar = tid >> 1;
    const int ah = (tid & 1) * (KS_ / 2);
    const int arow = bm + ar;
    const bool avalid = arow < M;
    const float* pA = nullptr;
    const float* pA2 = nullptr;
    const uint16_t* pH1 = nullptr;
    const uint16_t* pH2 = nullptr;
    bool attr_row = true;
    if (AMODE == 0) {
        pA = A1 + (size_t)(avalid ? arow : 0) * lda1;
    } else if (AMODE == 1) {
        int ai = avalid ? (arow / NOBJS) : 0;
        int oi = avalid ? (arow - ai * NOBJS) : 0;
        pH1 = H1 + (size_t)ai * ldh;
        pH2 = H2 + (size_t)oi * ldh;
    } else if (AMODE == 2) {
        pA = A1 + (size_t)(avalid ? arow : 0) * lda1;
        pA2 = A2 + (size_t)(avalid ? arow : 0) * lda2;
    } else {
        pA = A1 + (size_t)(avalid ? arow : 0) * lda1;
        attr_row = arow < NATTRS;
    }

    float acc[4][NI][4];
#pragma unroll
    for (int i = 0; i < 4; i++)
#pragma unroll
        for (int j = 0; j < NI; j++)
#pragma unroll
            for (int c = 0; c < 4; c++) acc[i][j][c] = 0.0f;

    float va[KS_ / 2];
    uint4 vh[GH];
    auto load_A = [&](int kb) {
        int k0 = kb + ah;
        if (AMODE == 1) {
#pragma unroll
            for (int g = 0; g < GH; g++) {
                int kg = k0 + g * 8;
                if (avalid && kg < K) {
                    vh[g] = h2addrelu4(*(const uint4*)(pH1 + kg),
                                       *(const uint4*)(pH2 + kg));
                } else {
                    vh[g] = make_uint4(0, 0, 0, 0);
                }
            }
            return;
        }
#pragma unroll
        for (int q = 0; q < KS_ / 2; q++) va[q] = 0.0f;
#pragma unroll
        for (int g = 0; g < KS_ / 8; g++) {
            int kg = k0 + g * 4;
            if (!avalid || kg >= K) continue;
            const float* src = nullptr;
            if (AMODE == 0) {
                src = pA + kg;
            } else if (AMODE == 2) {
                src = (kg < K1) ? (pA + kg) : (pA2 + (kg - K1));
            } else {
                bool use = attr_row ? (kg < K1) : (kg >= K1);
                if (!use) continue;
                src = attr_row ? (pA + kg) : (pA + (kg - K1));
            }
            float4 x = *(const float4*)(src);
            va[g*4+0] = x.x; va[g*4+1] = x.y; va[g*4+2] = x.z; va[g*4+3] = x.w;
        }
    };
    auto sts_A = [&](int buf) {
        const int base = buf * STRIDE;
        uint32_t off = (uint32_t)(ar * RB + ah * 2);
        if (AMODE == 1) {
#pragma unroll
            for (int g = 0; g < GH; g++)
                *(uint4*)(smem + base + AhiO + off + g * 16) = vh[g];
            return;
        }
#pragma unroll
        for (int g = 0; g < GH; g++) {
            union { uint16_t b[8]; uint4 u; } Uh, Ul;
#pragma unroll
            for (int q = 0; q < 8; q++) {
                float v = va[g * 8 + q];
                if (SPLIT) {
                    __nv_bfloat16 h = __float2bfloat16(v);
                    Uh.b[q] = __bfloat16_as_ushort(h);
                    Ul.b[q] = __bfloat16_as_ushort(__float2bfloat16(v - __bfloat162float(h)));
                } else {
                    Uh.b[q] = __half_as_ushort(__float2half_rn(v));
                }
            }
            *(uint4*)(smem + base + AhiO + off + g * 16) = Uh.u;
            if (SPLIT) *(uint4*)(smem + base + AloO + off + g * 16) = Ul.u;
        }
    };
    auto load_B = [&](int kb, int buf) {
        const int base = buf * STRIDE;
        constexpr int CPR = KS_ / 8;          // 16B chunks per row
        const int total = NT_ * CPR * NPLA;
        for (int i = tid; i < total; i += 256) {
            int plane = (i >= NT_ * CPR) ? 1 : 0;
            int v = i - plane * NT_ * CPR;
            int row = v / CPR;
            int c = v - row * CPR;
            int k0 = kb + c * 8;
            uint32_t doff = (uint32_t)(base + (plane ? BloO : BhiO) + row * RB + c * 16);
            if ((bn + row) < NB && k0 < K) {
                const uint16_t* src = (plane ? Blo : Bhi) + (size_t)(bn + row) * ldb + k0;
                cp16(sb + doff, src);
            } else {
                *(uint4*)(smem + doff) = make_uint4(0u, 0u, 0u, 0u);
            }
        }
    };

    const int NST = (K + KS_ - 1) / KS_;
    load_A(0);
    sts_A(0);
    load_B(0, 0);
    cp_commit();
    cp_wait0();
    __syncthreads();

    const int arowf = lane & 15;
    const int akf = ((lane >> 4) & 1) * 8;
    const int brow = lane & 7;
    const int bkf = ((lane >> 3) & 1) * 8;
    const int browx = (lane & 7) + ((lane & 16) >> 1);   // paired-x4 row within 16
    const int bkx = (lane & 8);                           // paired-x4 k-half select

    for (int st = 0; st < NST; st++) {
        const int cur = st & 1;
        const int nxt = cur ^ 1;
        const bool hasnext = (st + 1) < NST;
        if (hasnext) {
            load_A((st + 1) * KS_);
            load_B((st + 1) * KS_, nxt);
            cp_commit();
        }
        const int cbase = cur * STRIDE;
#pragma unroll
        for (int sub = 0; sub < NSUB; sub++) {
            if (st * KS_ + sub * 16 >= K) break;
            const int kcol = (sub * 16 + akf) * 2;
            const int kcolb = (sub * 16 + bkf) * 2;
            const int kcolx = (sub * 16 + bkx) * 2;
            uint32_t afh[4][4], afl[4][4];
#pragma unroll
            for (int mi = 0; mi < 4; mi++) {
                int m0 = wm * 64 + mi * 16;
                ldmA4(afh[mi], sb + cbase + AhiO + (m0 + arowf) * RB + kcol);
                if (SPLIT)
                    ldmA4(afl[mi], sb + cbase + AloO + (m0 + arowf) * RB + kcol);
            }
            uint32_t bfh[NI][2], bfl[NI][2];
#pragma unroll
            for (int ni = 0; ni + 1 < NI; ni += 2) {
                int n0 = wn * (NT_ / 4) + ni * 8;
                ldmB4(bfh[ni], bfh[ni + 1],
                      sb + cbase + BhiO + (n0 + browx) * RB + kcolx);
                if (SPLIT)
                    ldmB4(bfl[ni], bfl[ni + 1],
                          sb + cbase + BloO + (n0 + browx) * RB + kcolx);
            }
            if (NI & 1) {
                constexpr int ni = NI - 1;
                int n0 = wn * (NT_ / 4) + ni * 8;
                ldmB2(bfh[ni], sb + cbase + BhiO + (n0 + brow) * RB + kcolb);
                if (SPLIT)
                    ldmB2(bfl[ni], sb + cbase + BloO + (n0 + brow) * RB + kcolb);
            }
#pragma unroll
            for (int mi = 0; mi < 4; mi++)
#pragma unroll
                for (int ni = 0; ni < NI; ni++) {
                    if (SPLIT) {
                        mma_bf16(acc[mi][ni], afh[mi], bfh[ni]);
                        mma_bf16(acc[mi][ni], afh[mi], bfl[ni]);
                        mma_bf16(acc[mi][ni], afl[mi], bfh[ni]);
                    } else {
                        mma_f16(acc[mi][ni], afh[mi], bfh[ni]);
                    }
                }
        }
        if (hasnext) sts_A(nxt);
        cp_wait0();
        __syncthreads();
    }

    // epilogue
#pragma unroll
    for (int mi = 0; mi < 4; mi++) {
#pragma unroll
        for (int ni = 0; ni < NI; ni++) {
            int m0 = bm + wm * 64 + mi * 16 + (lane >> 2);
            int n0 = bn + wn * (NT_ / 4) + ni * 8 + (lane & 3) * 2;
            if (n0 >= NB) continue;
            float b0 = bias ? bias[n0] : 0.0f;
            float b1v = bias ? bias[n0 + 1] : 0.0f;
            float v0 = acc[mi][ni][0] + b0, v1 = acc[mi][ni][1] + b1v;
            float v2 = acc[mi][ni][2] + b0, v3 = acc[mi][ni][3] + b1v;
            if (RELU) {
                v0 = fmaxf(v0, 0.0f); v1 = fmaxf(v1, 0.0f);
                v2 = fmaxf(v2, 0.0f); v3 = fmaxf(v3, 0.0f);
            }
            if (m0 < M) *(float2*)(C + (size_t)m0 * ldc + n0) = make_float2(v0, v1);
            if (m0 + 8 < M) *(float2*)(C + (size_t)(m0 + 8) * ldc + n0) = make_float2(v2, v3);
        }
    }
}

// ---------------- host ----------------
static inline int ceildiv(int a, int b) { return (a + b - 1) / b; }

extern "C" void kernel_launch(void* const* d_in, const int* in_sizes, int n_in,
                              void* d_out, int out_size) {
    const float* img   = (const float*)d_in[0];
    const float* nodes = (const float*)d_in[1];
    const int*   esrc  = (const int*)d_in[2];
    const int*   edst  = (const int*)d_in[3];
    const float* W1l   = (const float*)d_in[4];
    const float* b1    = (const float*)d_in[5];
    const float* W1r   = (const float*)d_in[6];
    const float* W2l   = (const float*)d_in[7];
    const float* b2    = (const float*)d_in[8];
    const float* W2r   = (const float*)d_in[9];
    const float* Wp1   = (const float*)d_in[10];
    const float* bp1   = (const float*)d_in[11];
    const float* Wp2   = (const float*)d_in[12];
    const float* bp2   = (const float*)d_in[13];
    const float* gp    = (const float*)d_in[14];
    const float* bpn   = (const float*)d_in[15];
    const float* Wi1   = (const float*)d_in[16];
    const float* bi1   = (const float*)d_in[17];
    const float* Wi2   = (const float*)d_in[18];
    const float* bi2   = (const float*)d_in[19];
    const float* Wi3   = (const float*)d_in[20];
    const float* bi3   = (const float*)d_in[21];
    const float* gi    = (const float*)d_in[22];
    const float* bin_  = (const float*)d_in[23];
    float* out = (float*)d_out;

    void* p;
    cudaGetSymbolAddress(&p, g_scratch);
    float* S0 = (float*)p;
    uint16_t *w1h, *w1l_, *w2h, *w2l_, *wp1h, *wp1l, *wi1h, *wi1l,
             *wi2h, *wi2l, *wi3h, *wi3l, *wp2h, *Ph, *pah, *poh;
    cudaGetSymbolAddress(&p, g_w1c_hi); w1h  = (uint16_t*)p;
    cudaGetSymbolAddress(&p, g_w1c_lo); w1l_ = (uint16_t*)p;
    cudaGetSymbolAddress(&p, g_w2c_hi); w2h  = (uint16_t*)p;
    cudaGetSymbolAddress(&p, g_w2c_lo); w2l_ = (uint16_t*)p;
    cudaGetSymbolAddress(&p, g_wp1_hi); wp1h = (uint16_t*)p;
    cudaGetSymbolAddress(&p, g_wp1_lo); wp1l = (uint16_t*)p;
    cudaGetSymbolAddress(&p, g_wi1_hi); wi1h = (uint16_t*)p;
    cudaGetSymbolAddress(&p, g_wi1_lo); wi1l = (uint16_t*)p;
    cudaGetSymbolAddress(&p, g_wi2_hi); wi2h = (uint16_t*)p;
    cudaGetSymbolAddress(&p, g_wi2_lo); wi2l = (uint16_t*)p;
    cudaGetSymbolAddress(&p, g_wi3_hi); wi3h = (uint16_t*)p;
    cudaGetSymbolAddress(&p, g_wi3_lo); wi3l = (uint16_t*)p;
    cudaGetSymbolAddress(&p, g_wp2h);   wp2h = (uint16_t*)p;
    cudaGetSymbolAddress(&p, g_ph);     Ph   = (uint16_t*)p;
    cudaGetSymbolAddress(&p, g_pah);    pah  = (uint16_t*)p;
    cudaGetSymbolAddress(&p, g_poh);    poh  = (uint16_t*)p;

    float* adj   = S0 + OFF_ADJ;
    float* mean1 = S0 + OFF_MEAN1;
    float* h     = S0 + OFF_H;
    float* T2    = S0 + OFF_T2;
    float* on    = S0 + OFF_ON;
    float* PP    = S0 + OFF_PP;
    float* Q     = S0 + OFF_Q;
    float* i1    = S0 + OFF_I1;
    float* i2    = S0 + OFF_I2;
    float* i3    = S0 + OFF_I3;

    const int SM_S128 = 2 * (2 * (128 * 80) + 2 * (128 * 80));    // 81920 (KS32)
    const int SM_S160 = 2 * (2 * (128 * 80) + 2 * (160 * 80));    // 92160 (KS32)
    const int SM_F160 = 2 * ((128 * 144) + (160 * 144));          // 82944 (KS64)
    cudaFuncSetAttribute(mma2_kernel<2,1,1,128,32>, cudaFuncAttributeMaxDynamicSharedMemorySize, SM_S128);
    cudaFuncSetAttribute(mma2_kernel<0,1,0,128,32>, cudaFuncAttributeMaxDynamicSharedMemorySize, SM_S128);
    cudaFuncSetAttribute(mma2_kernel<0,1,1,128,32>, cudaFuncAttributeMaxDynamicSharedMemorySize, SM_S128);
    cudaFuncSetAttribute(mma2_kernel<3,1,0,160,32>, cudaFuncAttributeMaxDynamicSharedMemorySize, SM_S160);
    cudaFuncSetAttribute(mma2_kernel<0,1,0,160,32>, cudaFuncAttributeMaxDynamicSharedMemorySize, SM_S160);
    cudaFuncSetAttribute(mma2_kernel<1,0,0,160,64>, cudaFuncAttributeMaxDynamicSharedMemorySize, SM_F160);
    cudaFuncSetAttribute(mma2_kernel<0,0,0,160,64>, cudaFuncAttributeMaxDynamicSharedMemorySize, SM_F160);

    // ---- graph: dense normalized adjacency ----
    {
        int n = NNODES * NNODES;
        zero_kernel<<<(n + 255) / 256, 256>>>(adj, n);
        edge_count_kernel<<<(NEDGES + 255) / 256, 256>>>(esrc, edst, adj);
        row_norm_kernel<<<NNODES, 256>>>(adj);
    }

    // ---- weight prep (vectorized split to bf16 hi/lo; Wp2 to fp16) ----
    {
        int n8;
        n8 = DHID * 1024 / 8;
        splitcat8_kernel<<<(n8 + 255) / 256, 256>>>(W1l, DIN, W1r, DIN, w1h, w1l_, 1024, DHID);
        n8 = 512 * DHID / 8;
        splitcat8_kernel<<<(n8 + 255) / 256, 256>>>(W2l, DHID, nullptr, 0, w2h, w2l_, DHID, 512);
        splitcat8_kernel<<<(n8 + 255) / 256, 256>>>(W2r, DHID, nullptr, 0,
                                                    w2h + (size_t)512 * DHID,
                                                    w2l_ + (size_t)512 * DHID, DHID, 512);
        n8 = P1D * 1024 / 8;
        splitcat8_kernel<<<(n8 + 255) / 256, 256>>>(Wp1, 1024, nullptr, 0, wp1h, wp1l, 1024, P1D);
        n8 = 768 * FEATD / 8;
        splitcat8_kernel<<<(n8 + 255) / 256, 256>>>(Wi1, FEATD, nullptr, 0, wi1h, wi1l, FEATD, 768);
        n8 = 1000 * 768 / 8;
        splitcat8_kernel<<<(n8 + 255) / 256, 256>>>(Wi2, 768, nullptr, 0, wi2h, wi2l, 768, 1000);
        n8 = EMBD * 1024 / 8;
        splitcat8_kernel<<<(n8 + 255) / 256, 256>>>(Wi3, 1000, nullptr, 0, wi3h, wi3l, 1024, EMBD);
        n8 = EMBD * P1D / 8;
        tohalf8_kernel<<<(n8 + 255) / 256, 256>>>(Wp2, wp2h, n8);
    }

    // ---- mean1 = adj @ nodes  [650x512] (fp32 SIMT small) ----
    nn_small_kernel<<<dim3(DIN / 64, ceildiv(NNODES, 64)), 256>>>(
        adj, NNODES, nodes, DIN, nullptr, nullptr, 0, mean1, DIN, NNODES, DIN, NNODES);

    // ---- h = relu([mean1|nodes] @ [W1l|W1r]^T + b1)  M=650,N=4096,K=1024 ----
    mma2_kernel<2,1,1,128,32><<<dim3(DHID / 128, ceildiv(NNODES, 128)), 256, SM_S128>>>(
        mean1, DIN, nodes, DIN, DIN, nullptr, nullptr, 0,
        w1h, w1l_, 1024, h, DHID, NNODES, DHID, 1024, b1, nullptr);

    // ---- T2 = h @ [W2l;W2r]^T  M=650,N=1024,K=4096 ----
    mma2_kernel<0,1,0,128,32><<<dim3(1024 / 128, ceildiv(NNODES, 128)), 256, SM_S128>>>(
        h, DHID, nullptr, 0, 0, nullptr, nullptr, 0,
        w2h, w2l_, DHID, T2, 1024, NNODES, 1024, DHID, nullptr, nullptr);

    // ---- on = adj @ T2[:, :512] + b2 + T2[:, 512:]  [650x512] ----
    nn_small_kernel<<<dim3(DNODE / 64, ceildiv(NNODES, 64)), 256>>>(
        adj, NNODES, T2, 1024, b2, T2 + 512, 1024, on, DNODE, NNODES, DNODE, NNODES);

    // ---- PP = blockdiag(on) @ Wp1^T  M=650,N=1200,K=1024 ----
    mma2_kernel<3,1,0,160,32><<<dim3(ceildiv(P1D, 160), ceildiv(NNODES, 128)), 256, SM_S160>>>(
        on, DNODE, nullptr, 0, DNODE, nullptr, nullptr, 0,
        wp1h, wp1l, 1024, PP, P1D, NNODES, P1D, 1024, nullptr, nullptr);

    // ---- PP -> fp16 tables (bp1 folded into pah) ----
    {
        int n = NNODES * P1D;
        pp2half_kernel<<<(n + 255) / 256, 256>>>(PP, bp1, pah, poh);
    }

    // ---- Q = relu16(pah_i + poh_j) @ Wp2^T + bp2  (fp16 tables, KS=64) ----
    mma2_kernel<1,0,0,160,64><<<dim3(EMBD / 160, ceildiv(NPAIRS, 128)), 256, SM_F160>>>(
        nullptr, 0, nullptr, 0, 0, pah, poh, P1D,
        wp2h, nullptr, P1D, Q, EMBD, NPAIRS, EMBD, P1D, bp2, nullptr);

    // ---- LN rows of Q -> fp16 P ----
    ln_half_kernel<<<NPAIRS, 256>>>(Q, gp, bpn, Ph);

    // ---- image MLP (split-bf16) ----
    zero_kernel<<<(BATCH * 1024 + 255) / 256, 256>>>(i2, BATCH * 1024);
    mma2_kernel<0,1,1,128,32><<<dim3(768 / 128, ceildiv(BATCH, 128)), 256, SM_S128>>>(
        img, FEATD, nullptr, 0, 0, nullptr, nullptr, 0,
        wi1h, wi1l, FEATD, i1, 768, BATCH, 768, FEATD, bi1, nullptr);
    mma2_kernel<0,1,1,128,32><<<dim3(ceildiv(1000, 128), ceildiv(BATCH, 128)), 256, SM_S128>>>(
        i1, 768, nullptr, 0, 0, nullptr, nullptr, 0,
        wi2h, wi2l, 768, i2, 1024, BATCH, 1000, 768, bi2, nullptr);
    mma2_kernel<0,1,0,160,32><<<dim3(EMBD / 160, ceildiv(BATCH, 128)), 256, SM_S160>>>(
        i2, 1024, nullptr, 0, 0, nullptr, nullptr, 0,
        wi3h, wi3l, 1024, i3, EMBD, BATCH, EMBD, 1024, bi3, nullptr);
    ln_kernel<<<BATCH, 256>>>(i3, gi, bin_, EMBD);

    // ---- out = iLN @ P^T  (fp16, KS=64)  [256 x 100000] ----
    mma2_kernel<0,0,0,160,64><<<dim3(NPAIRS / 160, ceildiv(BATCH, 128)), 256, SM_F160>>>(
        i3, EMBD, nullptr, 0, 0, nullptr, nullptr, 0,
        Ph, nullptr, EMBD, out, NPAIRS, BATCH, NPAIRS, EMBD, nullptr, nullptr);
}

// round 14
// speedup vs baseline: 1.1895x; 1.1895x over previous
#include <cuda_runtime.h>
#include <cuda_fp16.h>
#include <cuda_bf16.h>
#include <cstdint>

#define NATTRS 250
#define NOBJS  400
#define NNODES 650
#define NEDGES 100000
#define DIN    512
#define DHID   4096
#define DNODE  512
#define FEATD  2048
#define EMBD   800
#define BATCH  256
#define P1D    1200
#define NPAIRS (NATTRS * NOBJS)
#define LNEPS  1e-5f

// ---------------- scratch (single __device__ global; no allocs) ----------------
#define OFF_ADJ    0ull
#define OFF_MEAN1  (OFF_ADJ   + (size_t)NNODES * NNODES)
#define OFF_H      (OFF_MEAN1 + (size_t)NNODES * DIN)
#define OFF_T2     (OFF_H     + (size_t)NNODES * DHID)
#define OFF_ON     (OFF_T2    + (size_t)NNODES * 1024)
#define OFF_PP     (OFF_ON    + (size_t)NNODES * DNODE)
#define OFF_Q      (OFF_PP    + (size_t)NNODES * P1D)
#define OFF_I1     (OFF_Q     + (size_t)NPAIRS * EMBD)
#define OFF_I2     (OFF_I1    + (size_t)BATCH * 768)
#define OFF_I3     (OFF_I2    + (size_t)BATCH * 1024)
#define OFF_PART   (OFF_I3    + (size_t)BATCH * EMBD)
#define PART_ELEMS ((size_t)4 * NNODES * P1D)   /* max: PP splitk4 */
#define SCRATCH_ELEMS (OFF_PART + PART_ELEMS)

__device__ float g_scratch[SCRATCH_ELEMS];

// split-bf16 weight buffers
__device__ uint16_t g_w1c_hi[(size_t)DHID * 1024];
__device__ uint16_t g_w1c_lo[(size_t)DHID * 1024];
__device__ uint16_t g_w2c_hi[(size_t)1024 * DHID];
__device__ uint16_t g_w2c_lo[(size_t)1024 * DHID];
__device__ uint16_t g_wp1_hi[(size_t)P1D * 1024];
__device__ uint16_t g_wp1_lo[(size_t)P1D * 1024];
__device__ uint16_t g_wi1_hi[(size_t)768 * FEATD];
__device__ uint16_t g_wi1_lo[(size_t)768 * FEATD];
__device__ uint16_t g_wi2_hi[(size_t)1000 * 768];
__device__ uint16_t g_wi2_lo[(size_t)1000 * 768];
__device__ uint16_t g_wi3_hi[(size_t)EMBD * 1024];
__device__ uint16_t g_wi3_lo[(size_t)EMBD * 1024];
// fp16 buffers
__device__ uint16_t g_wp2h[(size_t)EMBD * P1D];
__device__ uint16_t g_ph[(size_t)NPAIRS * EMBD];
__device__ uint16_t g_pah[(size_t)NATTRS * P1D];
__device__ uint16_t g_poh[(size_t)NOBJS * P1D];

// ---------------- small kernels ----------------
__global__ void zero_kernel(float* p, int n) {
    int i = blockIdx.x * blockDim.x + threadIdx.x;
    if (i < n) p[i] = 0.0f;
}

__global__ void edge_count_kernel(const int* __restrict__ src,
                                  const int* __restrict__ dst,
                                  float* __restrict__ adj) {
    int e = blockIdx.x * blockDim.x + threadIdx.x;
    if (e < NEDGES) atomicAdd(&adj[(size_t)dst[e] * NNODES + src[e]], 1.0f);
}

__global__ void row_norm_kernel(float* __restrict__ adj) {
    __shared__ float sbuf[32];
    int r = blockIdx.x;
    int tid = threadIdx.x;
    float s = 0.0f;
    float* row = adj + (size_t)r * NNODES;
    for (int c = tid; c < NNODES; c += blockDim.x) s += row[c];
    for (int o = 16; o > 0; o >>= 1) s += __shfl_down_sync(0xffffffffu, s, o);
    if ((tid & 31) == 0) sbuf[tid >> 5] = s;
    __syncthreads();
    int nw = blockDim.x >> 5;
    if (tid < 32) {
        s = (tid < nw) ? sbuf[tid] : 0.0f;
        for (int o = 16; o > 0; o >>= 1) s += __shfl_down_sync(0xffffffffu, s, o);
        if (tid == 0) sbuf[0] = s;
    }
    __syncthreads();
    float inv = 1.0f / fmaxf(sbuf[0], 1.0f);
    for (int c = tid; c < NNODES; c += blockDim.x) row[c] *= inv;
}

// vectorized split-concat (x8): out row k<K1 from X1, else X2; pad 0
__global__ void splitcat8_kernel(const float* __restrict__ X1, int K1,
                                 const float* __restrict__ X2, int K2,
                                 uint16_t* __restrict__ hi, uint16_t* __restrict__ lo,
                                 int ldo, int Nrows) {
    int g = blockIdx.x * blockDim.x + threadIdx.x;
    int total = Nrows * ldo / 8;
    if (g >= total) return;
    int base = g * 8;
    int n = base / ldo, k = base - n * ldo;
    float v[8];
    if (k + 8 <= K1) {
        const float4* s = (const float4*)(X1 + (size_t)n * K1 + k);
        float4 a = s[0], b = s[1];
        v[0]=a.x; v[1]=a.y; v[2]=a.z; v[3]=a.w; v[4]=b.x; v[5]=b.y; v[6]=b.z; v[7]=b.w;
    } else if (k >= K1 && k + 8 <= K1 + K2) {
        const float4* s = (const float4*)(X2 + (size_t)n * K2 + (k - K1));
        float4 a = s[0], b = s[1];
        v[0]=a.x; v[1]=a.y; v[2]=a.z; v[3]=a.w; v[4]=b.x; v[5]=b.y; v[6]=b.z; v[7]=b.w;
    } else {
#pragma unroll
        for (int q = 0; q < 8; q++) {
            int kk = k + q;
            v[q] = (kk < K1) ? X1[(size_t)n * K1 + kk]
                 : (kk < K1 + K2 ? X2[(size_t)n * K2 + (kk - K1)] : 0.0f);
        }
    }
    union { uint16_t b[8]; uint4 u; } Uh, Ul;
#pragma unroll
    for (int q = 0; q < 8; q++) {
        __nv_bfloat16 h = __float2bfloat16(v[q]);
        Uh.b[q] = __bfloat16_as_ushort(h);
        Ul.b[q] = __bfloat16_as_ushort(__float2bfloat16(v[q] - __bfloat162float(h)));
    }
    *(uint4*)(hi + base) = Uh.u;
    *(uint4*)(lo + base) = Ul.u;
}

__global__ void tohalf8_kernel(const float* __restrict__ x,
                               uint16_t* __restrict__ y, int n8) {
    int g = blockIdx.x * blockDim.x + threadIdx.x;
    if (g >= n8) return;
    const float4* s = (const float4*)(x + g * 8);
    float4 a = s[0], b = s[1];
    union { uint16_t h[8]; uint4 u; } U;
    U.h[0] = __half_as_ushort(__float2half_rn(a.x));
    U.h[1] = __half_as_ushort(__float2half_rn(a.y));
    U.h[2] = __half_as_ushort(__float2half_rn(a.z));
    U.h[3] = __half_as_ushort(__float2half_rn(a.w));
    U.h[4] = __half_as_ushort(__float2half_rn(b.x));
    U.h[5] = __half_as_ushort(__float2half_rn(b.y));
    U.h[6] = __half_as_ushort(__float2half_rn(b.z));
    U.h[7] = __half_as_ushort(__float2half_rn(b.w));
    *(uint4*)(y + g * 8) = U.u;
}

// PP [650x1200] -> fp16 tables: pah = fp16(PP[:250] + bp1), poh = fp16(PP[250:])
__global__ void pp2half_kernel(const float* __restrict__ PP,
                               const float* __restrict__ bp1,
                               uint16_t* __restrict__ pah,
                               uint16_t* __restrict__ poh) {
    int i = blockIdx.x * blockDim.x + threadIdx.x;
    if (i >= NNODES * P1D) return;
    int r = i / P1D, k = i - r * P1D;
    float v = PP[i];
    if (r < NATTRS) {
        pah[(size_t)r * P1D + k] = __half_as_ushort(__float2half_rn(v + bp1[k]));
    } else {
        poh[(size_t)(r - NATTRS) * P1D + k] = __half_as_ushort(__float2half_rn(v));
    }
}

// sum split-K partials + bias (+relu) -> C
__global__ void reduce_parts_kernel(const float* __restrict__ part, size_t pstride,
                                    int nz, const float* __restrict__ bias, int relu,
                                    float* __restrict__ C, int ldc, int ldp,
                                    int M, int NB) {
    int i = blockIdx.x * blockDim.x + threadIdx.x;
    if (i >= M * NB) return;
    int m = i / NB, n = i - m * NB;
    float s = 0.0f;
    for (int z = 0; z < nz; z++)
        s += part[(size_t)z * pstride + (size_t)m * ldp + n];
    if (bias) s += bias[n];
    if (relu) s = fmaxf(s, 0.0f);
    C[(size_t)m * ldc + n] = s;
}

// in-place LayerNorm (fp32)
__global__ void ln_kernel(float* __restrict__ X,
                          const float* __restrict__ g,
                          const float* __restrict__ b, int D) {
    __shared__ float sA[32], sB[32];
    int r = blockIdx.x;
    int tid = threadIdx.x;
    float* x = X + (size_t)r * D;
    float s = 0.0f, s2 = 0.0f;
    for (int d = tid; d < D; d += blockDim.x) { float v = x[d]; s += v; s2 += v * v; }
    for (int o = 16; o > 0; o >>= 1) {
        s += __shfl_down_sync(0xffffffffu, s, o);
        s2 += __shfl_down_sync(0xffffffffu, s2, o);
    }
    if ((tid & 31) == 0) { sA[tid >> 5] = s; sB[tid >> 5] = s2; }
    __syncthreads();
    int nw = blockDim.x >> 5;
    if (tid < 32) {
        s = (tid < nw) ? sA[tid] : 0.0f;
        s2 = (tid < nw) ? sB[tid] : 0.0f;
        for (int o = 16; o > 0; o >>= 1) {
            s += __shfl_down_sync(0xffffffffu, s, o);
            s2 += __shfl_down_sync(0xffffffffu, s2, o);
        }
        if (tid == 0) { sA[0] = s; sB[0] = s2; }
    }
    __syncthreads();
    float invD = 1.0f / (float)D;
    float m = sA[0] * invD;
    float var = fmaxf(sB[0] * invD - m * m, 0.0f);
    float inv = rsqrtf(var + LNEPS);
    for (int d = tid; d < D; d += blockDim.x)
        x[d] = (x[d] - m) * inv * g[d] + b[d];
}

// LayerNorm of Q rows -> fp16 P
__global__ void ln_half_kernel(const float* __restrict__ Q,
                               const float* __restrict__ g,
                               const float* __restrict__ b,
                               uint16_t* __restrict__ Ph) {
    __shared__ float sA[32], sB[32];
    int r = blockIdx.x;
    int tid = threadIdx.x;
    const float* x = Q + (size_t)r * EMBD;
    float s = 0.0f, s2 = 0.0f;
    for (int d = tid; d < EMBD; d += blockDim.x) { float v = x[d]; s += v; s2 += v * v; }
    for (int o = 16; o > 0; o >>= 1) {
        s += __shfl_down_sync(0xffffffffu, s, o);
        s2 += __shfl_down_sync(0xffffffffu, s2, o);
    }
    if ((tid & 31) == 0) { sA[tid >> 5] = s; sB[tid >> 5] = s2; }
    __syncthreads();
    int nw = blockDim.x >> 5;
    if (tid < 32) {
        s = (tid < nw) ? sA[tid] : 0.0f;
        s2 = (tid < nw) ? sB[tid] : 0.0f;
        for (int o = 16; o > 0; o >>= 1) {
            s += __shfl_down_sync(0xffffffffu, s, o);
            s2 += __shfl_down_sync(0xffffffffu, s2, o);
        }
        if (tid == 0) { sA[0] = s; sB[0] = s2; }
    }
    __syncthreads();
    float invD = 1.0f / (float)EMBD;
    float m = sA[0] * invD;
    float var = fmaxf(sB[0] * invD - m * m, 0.0f);
    float inv = rsqrtf(var + LNEPS);
    for (int d = tid; d < EMBD; d += blockDim.x) {
        float p = (x[d] - m) * inv * g[d] + b[d];
        Ph[(size_t)r * EMBD + d] = __half_as_ushort(__float2half_rn(p));
    }
}

// ---------------- small fp32 NN gemm (64x64 tiles) ----------------
__global__ __launch_bounds__(256)
void nn_small_kernel(const float* __restrict__ A, int lda,
                     const float* __restrict__ B, int ldb,
                     const float* __restrict__ bias,
                     const float* __restrict__ extra, int lde,
                     float* __restrict__ C, int ldc,
                     int M, int N, int K) {
    __shared__ float As[16][68];
    __shared__ float Bs[16][68];
    int tid = threadIdx.x;
    int bm = blockIdx.y * 64, bn = blockIdx.x * 64;
    int tx = tid & 15, ty = tid >> 4;
    float acc[4][4];
#pragma unroll
    for (int i = 0; i < 4; i++)
#pragma unroll
        for (int j = 0; j < 4; j++) acc[i][j] = 0.0f;
    for (int k0 = 0; k0 < K; k0 += 16) {
        for (int e = tid; e < 1024; e += 256) {
            int row = e & 63, kk = e >> 6;
            int gm = bm + row, gk = k0 + kk, gn = bn + row;
            As[kk][row] = (gm < M && gk < K) ? A[(size_t)gm * lda + gk] : 0.0f;
            Bs[kk][row] = (gn < N && gk < K) ? B[(size_t)gk * ldb + gn] : 0.0f;
        }
        __syncthreads();
#pragma unroll
        for (int kk = 0; kk < 16; kk++) {
            float a[4], b[4];
#pragma unroll
            for (int i = 0; i < 4; i++) a[i] = As[kk][ty * 4 + i];
#pragma unroll
            for (int j = 0; j < 4; j++) b[j] = Bs[kk][tx * 4 + j];
#pragma unroll
            for (int i = 0; i < 4; i++)
#pragma unroll
                for (int j = 0; j < 4; j++) acc[i][j] += a[i] * b[j];
        }
        __syncthreads();
    }
#pragma unroll
    for (int i = 0; i < 4; i++) {
        int m = bm + ty * 4 + i;
        if (m >= M) continue;
#pragma unroll
        for (int j = 0; j < 4; j++) {
            int n = bn + tx * 4 + j;
            if (n >= N) continue;
            float v = acc[i][j];
            if (bias) v += bias[n];
            if (extra) v += extra[(size_t)m * lde + n];
            C[(size_t)m * ldc + n] = v;
        }
    }
}

// ================= generalized tensor-core GEMM =================
// C[M,NB] = A[M,K] @ B[NB,K]^T  (+bias), optional relu.
// SPLIT=1: 3-term split-bf16. SPLIT=0: single-term fp16.
// AMODE 0: A = A1 (fp32, lda1)
// AMODE 1: A[r,k] = relu_fp16(H1[r/NOBJS,k] + H2[r%NOBJS,k])  (fp16 tables; SPLIT=0)
// AMODE 2: A[r,k] = k<K1 ? A1[r,k] : A2[r,k-K1]
// AMODE 3: A[r,k] = r<NATTRS ? (k<K1 ? A1[r,k] : 0) : (k>=K1 ? A1[r,k-K1] : 0)
// Split-K: kchunk>0 -> this CTA covers K range [z*kchunk, min(K,(z+1)*kchunk)),
//          z = blockIdx.z, and writes to C + z*pstride (raw partials).
// CTA tile: 128(M) x NT_(N), K-stage KS_.

__device__ __forceinline__ uint32_t smem_u32(const void* p) {
    return (uint32_t)__cvta_generic_to_shared(p);
}
__device__ __forceinline__ void ldmA4(uint32_t r[4], uint32_t addr) {
    asm volatile("ldmatrix.sync.aligned.m8n8.x4.shared.b16 {%0,%1,%2,%3},[%4];\n"
                 : "=r"(r[0]), "=r"(r[1]), "=r"(r[2]), "=r"(r[3]) : "r"(addr));
}
__device__ __forceinline__ void ldmB2(uint32_t r[2], uint32_t addr) {
    asm volatile("ldmatrix.sync.aligned.m8n8.x2.shared.b16 {%0,%1},[%2];\n"
                 : "=r"(r[0]), "=r"(r[1]) : "r"(addr));
}
// paired B load: 2 n-groups (16 rows) x 16 k-cols in one ldmatrix.x4
__device__ __forceinline__ void ldmB4(uint32_t r0[2], uint32_t r1[2], uint32_t addr) {
    asm volatile("ldmatrix.sync.aligned.m8n8.x4.shared.b16 {%0,%1,%2,%3},[%4];\n"
                 : "=r"(r0[0]), "=r"(r0[1]), "=r"(r1[0]), "=r"(r1[1]) : "r"(addr));
}
__device__ __forceinline__ void mma_f16(float d[4], const uint32_t a[4],
                                        const uint32_t b[2]) {
    asm volatile(
        "mma.sync.aligned.m16n8k16.row.col.f32.f16.f16.f32 "
        "{%0,%1,%2,%3},{%4,%5,%6,%7},{%8,%9},{%0,%1,%2,%3};\n"
        : "+f"(d[0]), "+f"(d[1]), "+f"(d[2]), "+f"(d[3])
        : "r"(a[0]), "r"(a[1]), "r"(a[2]), "r"(a[3]), "r"(b[0]), "r"(b[1]));
}
__device__ __forceinline__ void mma_bf16(float d[4], const uint32_t a[4],
                                         const uint32_t b[2]) {
    asm volatile(
        "mma.sync.aligned.m16n8k16.row.col.f32.bf16.bf16.f32 "
        "{%0,%1,%2,%3},{%4,%5,%6,%7},{%8,%9},{%0,%1,%2,%3};\n"
        : "+f"(d[0]), "+f"(d[1]), "+f"(d[2]), "+f"(d[3])
        : "r"(a[0]), "r"(a[1]), "r"(a[2]), "r"(a[3]), "r"(b[0]), "r"(b[1]));
}
__device__ __forceinline__ void cp16(uint32_t dst, const void* src) {
    asm volatile("cp.async.cg.shared.global [%0], [%1], 16;\n" :: "r"(dst), "l"(src));
}
__device__ __forceinline__ void cp_commit() { asm volatile("cp.async.commit_group;\n"); }
__device__ __forceinline__ void cp_wait0()  { asm volatile("cp.async.wait_group 0;\n"); }

__device__ __forceinline__ uint32_t h2addrelu(uint32_t a, uint32_t b) {
    __half2 ha = *(__half2*)&a;
    __half2 hb = *(__half2*)&b;
    __half2 r = __hmax2(__hadd2(ha, hb), __float2half2_rn(0.0f));
    return *(uint32_t*)&r;
}
__device__ __forceinline__ uint4 h2addrelu4(uint4 a, uint4 b) {
    uint4 r;
    r.x = h2addrelu(a.x, b.x); r.y = h2addrelu(a.y, b.y);
    r.z = h2addrelu(a.z, b.z); r.w = h2addrelu(a.w, b.w);
    return r;
}

template <int AMODE, int SPLIT, int RELU, int NT_, int KS_>
__global__ __launch_bounds__(256)
void mma2_kernel(const float* __restrict__ A1, int lda1,
                 const float* __restrict__ A2, int lda2, int K1,
                 const uint16_t* __restrict__ H1,
                 const uint16_t* __restrict__ H2, int ldh,
                 const uint16_t* __restrict__ Bhi,
                 const uint16_t* __restrict__ Blo, int ldb,
                 float* __restrict__ C, int ldc,
                 int M, int NB, int K,
                 const float* __restrict__ bias,
                 int kchunk, size_t pstride) {
    constexpr int NI   = NT_ / 32;
    constexpr int RB   = (KS_ + 8) * 2;     // bytes per smem row (8-half pad)
    constexpr int ASZ  = 128 * RB;
    constexpr int BSZ  = NT_ * RB;
    constexpr int NPLA = SPLIT ? 2 : 1;
    constexpr int STRIDE = NPLA * (ASZ + BSZ);
    constexpr int AhiO = 0;
    constexpr int AloO = ASZ;
    constexpr int BhiO = NPLA * ASZ;
    constexpr int BloO = NPLA * ASZ + BSZ;
    constexpr int NSUB = KS_ / 16;
    constexpr int GH   = KS_ / 16;

    extern __shared__ char smem[];
    const uint32_t sb = smem_u32(smem);
    const int tid = threadIdx.x;
    const int warp = tid >> 5;
    const int lane = tid & 31;
    const int bm = blockIdx.y * 128;
    const int bn = blockIdx.x * NT_;
    const int wm = warp & 1;
    const int wn = warp >> 1;

    // split-K range
    int koff = 0, kend = K;
    if (kchunk > 0) {
        koff = blockIdx.z * kchunk;
        int ke = koff + kchunk;
        kend = ke < K ? ke : K;
        C += (size_t)blockIdx.z * pstride;
    }

    const int ar = tid >> 1;
    const int ah = (tid & 1) * (KS_ / 2);
    const int arow = bm + ar;
    const bool avalid = arow < M;
    const float* pA = nullptr;
    const float* pA2 = nullptr;
    const uint16_t* pH1 = nullptr;
    const uint16_t* pH2 = nullptr;
    bool attr_row = true;
    if (AMODE == 0) {
        pA = A1 + (size_t)(avalid ? arow : 0) * lda1;
    } else if (AMODE == 1) {
        int ai = avalid ? (arow / NOBJS) : 0;
        int oi = avalid ? (arow - ai * NOBJS) : 0;
        pH1 = H1 + (size_t)ai * ldh;
        pH2 = H2 + (size_t)oi * ldh;
    } else if (AMODE == 2) {
        pA = A1 + (size_t)(avalid ? arow : 0) * lda1;
        pA2 = A2 + (size_t)(avalid ? arow : 0) * lda2;
    } else {
        pA = A1 + (size_t)(avalid ? arow : 0) * lda1;
        attr_row = arow < NATTRS;
    }

    float acc[4][NI][4];
#pragma unroll
    for (int i = 0; i < 4; i++)
#pragma unroll
        for (int j = 0; j < NI; j++)
#pragma unroll
            for (int c = 0; c < 4; c++) acc[i][j][c] = 0.0f;

    float va[KS_ / 2];
    uint4 vh[GH];
    auto load_A = [&](int kb) {   // kb absolute
        int k0 = kb + ah;
        if (AMODE == 1) {
#pragma unroll
            for (int g = 0; g < GH; g++) {
                int kg = k0 + g * 8;
                if (avalid && kg < kend) {
                    vh[g] = h2addrelu4(*(const uint4*)(pH1 + kg),
                                       *(const uint4*)(pH2 + kg));
                } else {
                    vh[g] = make_uint4(0, 0, 0, 0);
                }
            }
            return;
        }
#pragma unroll
        for (int q = 0; q < KS_ / 2; q++) va[q] = 0.0f;
#pragma unroll
        for (int g = 0; g < KS_ / 8; g++) {
            int kg = k0 + g * 4;
            if (!avalid || kg >= kend) continue;
            const float* src = nullptr;
            if (AMODE == 0) {
                src = pA + kg;
            } else if (AMODE == 2) {
                src = (kg < K1) ? (pA + kg) : (pA2 + (kg - K1));
            } else {
                bool use = attr_row ? (kg < K1) : (kg >= K1);
                if (!use) continue;
                src = attr_row ? (pA + kg) : (pA + (kg - K1));
            }
            float4 x = *(const float4*)(src);
            va[g*4+0] = x.x; va[g*4+1] = x.y; va[g*4+2] = x.z; va[g*4+3] = x.w;
        }
    };
    auto sts_A = [&](int buf) {
        const int base = buf * STRIDE;
        uint32_t off = (uint32_t)(ar * RB + ah * 2);
        if (AMODE == 1) {
#pragma unroll
            for (int g = 0; g < GH; g++)
                *(uint4*)(smem + base + AhiO + off + g * 16) = vh[g];
            return;
        }
#pragma unroll
        for (int g = 0; g < GH; g++) {
            union { uint16_t b[8]; uint4 u; } Uh, Ul;
#pragma unroll
            for (int q = 0; q < 8; q++) {
                float v = va[g * 8 + q];
                if (SPLIT) {
                    __nv_bfloat16 h = __float2bfloat16(v);
                    Uh.b[q] = __bfloat16_as_ushort(h);
                    Ul.b[q] = __bfloat16_as_ushort(__float2bfloat16(v - __bfloat162float(h)));
                } else {
                    Uh.b[q] = __half_as_ushort(__float2half_rn(v));
                }
            }
            *(uint4*)(smem + base + AhiO + off + g * 16) = Uh.u;
            if (SPLIT) *(uint4*)(smem + base + AloO + off + g * 16) = Ul.u;
        }
    };
    auto load_B = [&](int kb, int buf) {   // kb absolute
        const int base = buf * STRIDE;
        constexpr int CPR = KS_ / 8;
        const int total = NT_ * CPR * NPLA;
        for (int i = tid; i < total; i += 256) {
            int plane = (i >= NT_ * CPR) ? 1 : 0;
            int v = i - plane * NT_ * CPR;
            int row = v / CPR;
            int c = v - row * CPR;
            int k0 = kb + c * 8;
            uint32_t doff = (uint32_t)(base + (plane ? BloO : BhiO) + row * RB + c * 16);
            if ((bn + row) < NB && k0 < kend) {
                const uint16_t* src = (plane ? Blo : Bhi) + (size_t)(bn + row) * ldb + k0;
                cp16(sb + doff, src);
            } else {
                *(uint4*)(smem + doff) = make_uint4(0u, 0u, 0u, 0u);
            }
        }
    };

    const int NST = (kend - koff + KS_ - 1) / KS_;
    load_A(koff);
    sts_A(0);
    load_B(koff, 0);
    cp_commit();
    cp_wait0();
    __syncthreads();

    const int arowf = lane & 15;
    const int akf = ((lane >> 4) & 1) * 8;
    const int brow = lane & 7;
    const int bkf = ((lane >> 3) & 1) * 8;
    const int browx = (lane & 7) + ((lane & 16) >> 1);
    const int bkx = (lane & 8);

    for (int st = 0; st < NST; st++) {
        const int cur = st & 1;
        const int nxt = cur ^ 1;
        const bool hasnext = (st + 1) < NST;
        if (hasnext) {
            load_A(koff + (st + 1) * KS_);
            load_B(koff + (st + 1) * KS_, nxt);
            cp_commit();
        }
        const int cbase = cur * STRIDE;
#pragma unroll
        for (int sub = 0; sub < NSUB; sub++) {
            if (koff + st * KS_ + sub * 16 >= kend) break;
            const int kcol = (sub * 16 + akf) * 2;
            const int kcolb = (sub * 16 + bkf) * 2;
            const int kcolx = (sub * 16 + bkx) * 2;
            uint32_t afh[4][4], afl[4][4];
#pragma unroll
            for (int mi = 0; mi < 4; mi++) {
                int m0 = wm * 64 + mi * 16;
                ldmA4(afh[mi], sb + cbase + AhiO + (m0 + arowf) * RB + kcol);
                if (SPLIT)
                    ldmA4(afl[mi], sb + cbase + AloO + (m0 + arowf) * RB + kcol);
            }
            uint32_t bfh[NI][2], bfl[NI][2];
#pragma unroll
            for (int ni = 0; ni + 1 < NI; ni += 2) {
                int n0 = wn * (NT_ / 4) + ni * 8;
                ldmB4(bfh[ni], bfh[ni + 1],
                      sb + cbase + BhiO + (n0 + browx) * RB + kcolx);
                if (SPLIT)
                    ldmB4(bfl[ni], bfl[ni + 1],
                          sb + cbase + BloO + (n0 + browx) * RB + kcolx);
            }
            if (NI & 1) {
                constexpr int ni = NI - 1;
                int n0 = wn * (NT_ / 4) + ni * 8;
                ldmB2(bfh[ni], sb + cbase + BhiO + (n0 + brow) * RB + kcolb);
                if (SPLIT)
                    ldmB2(bfl[ni], sb + cbase + BloO + (n0 + brow) * RB + kcolb);
            }
#pragma unroll
            for (int mi = 0; mi < 4; mi++)
#pragma unroll
                for (int ni = 0; ni < NI; ni++) {
                    if (SPLIT) {
                        mma_bf16(acc[mi][ni], afh[mi], bfh[ni]);
                        mma_bf16(acc[mi][ni], afh[mi], bfl[ni]);
                        mma_bf16(acc[mi][ni], afl[mi], bfh[ni]);
                    } else {
                        mma_f16(acc[mi][ni], afh[mi], bfh[ni]);
                    }
                }
        }
        if (hasnext) sts_A(nxt);
        cp_wait0();
        __syncthreads();
    }

    // epilogue
#pragma unroll
    for (int mi = 0; mi < 4; mi++) {
#pragma unroll
        for (int ni = 0; ni < NI; ni++) {
            int m0 = bm + wm * 64 + mi * 16 + (lane >> 2);
            int n0 = bn + wn * (NT_ / 4) + ni * 8 + (lane & 3) * 2;
            if (n0 >= NB) continue;
            float b0 = bias ? bias[n0] : 0.0f;
            float b1v = bias ? bias[n0 + 1] : 0.0f;
            float v0 = acc[mi][ni][0] + b0, v1 = acc[mi][ni][1] + b1v;
            float v2 = acc[mi][ni][2] + b0, v3 = acc[mi][ni][3] + b1v;
            if (RELU) {
                v0 = fmaxf(v0, 0.0f); v1 = fmaxf(v1, 0.0f);
                v2 = fmaxf(v2, 0.0f); v3 = fmaxf(v3, 0.0f);
            }
            if (m0 < M) *(float2*)(C + (size_t)m0 * ldc + n0) = make_float2(v0, v1);
            if (m0 + 8 < M) *(float2*)(C + (size_t)(m0 + 8) * ldc + n0) = make_float2(v2, v3);
        }
    }
}

// ---------------- host ----------------
static inline int ceildiv(int a, int b) { return (a + b - 1) / b; }

extern "C" void kernel_launch(void* const* d_in, const int* in_sizes, int n_in,
                              void* d_out, int out_size) {
    const float* img   = (const float*)d_in[0];
    const float* nodes = (const float*)d_in[1];
    const int*   esrc  = (const int*)d_in[2];
    const int*   edst  = (const int*)d_in[3];
    const float* W1l   = (const float*)d_in[4];
    const float* b1    = (const float*)d_in[5];
    const float* W1r   = (const float*)d_in[6];
    const float* W2l   = (const float*)d_in[7];
    const float* b2    = (const float*)d_in[8];
    const float* W2r   = (const float*)d_in[9];
    const float* Wp1   = (const float*)d_in[10];
    const float* bp1   = (const float*)d_in[11];
    const float* Wp2   = (const float*)d_in[12];
    const float* bp2   = (const float*)d_in[13];
    const float* gp    = (const float*)d_in[14];
    const float* bpn   = (const float*)d_in[15];
    const float* Wi1   = (const float*)d_in[16];
    const float* bi1   = (const float*)d_in[17];
    const float* Wi2   = (const float*)d_in[18];
    const float* bi2   = (const float*)d_in[19];
    const float* Wi3   = (const float*)d_in[20];
    const float* bi3   = (const float*)d_in[21];
    const float* gi    = (const float*)d_in[22];
    const float* bin_  = (const float*)d_in[23];
    float* out = (float*)d_out;

    void* p;
    cudaGetSymbolAddress(&p, g_scratch);
    float* S0 = (float*)p;
    uint16_t *w1h, *w1l_, *w2h, *w2l_, *wp1h, *wp1l, *wi1h, *wi1l,
             *wi2h, *wi2l, *wi3h, *wi3l, *wp2h, *Ph, *pah, *poh;
    cudaGetSymbolAddress(&p, g_w1c_hi); w1h  = (uint16_t*)p;
    cudaGetSymbolAddress(&p, g_w1c_lo); w1l_ = (uint16_t*)p;
    cudaGetSymbolAddress(&p, g_w2c_hi); w2h  = (uint16_t*)p;
    cudaGetSymbolAddress(&p, g_w2c_lo); w2l_ = (uint16_t*)p;
    cudaGetSymbolAddress(&p, g_wp1_hi); wp1h = (uint16_t*)p;
    cudaGetSymbolAddress(&p, g_wp1_lo); wp1l = (uint16_t*)p;
    cudaGetSymbolAddress(&p, g_wi1_hi); wi1h = (uint16_t*)p;
    cudaGetSymbolAddress(&p, g_wi1_lo); wi1l = (uint16_t*)p;
    cudaGetSymbolAddress(&p, g_wi2_hi); wi2h = (uint16_t*)p;
    cudaGetSymbolAddress(&p, g_wi2_lo); wi2l = (uint16_t*)p;
    cudaGetSymbolAddress(&p, g_wi3_hi); wi3h = (uint16_t*)p;
    cudaGetSymbolAddress(&p, g_wi3_lo); wi3l = (uint16_t*)p;
    cudaGetSymbolAddress(&p, g_wp2h);   wp2h = (uint16_t*)p;
    cudaGetSymbolAddress(&p, g_ph);     Ph   = (uint16_t*)p;
    cudaGetSymbolAddress(&p, g_pah);    pah  = (uint16_t*)p;
    cudaGetSymbolAddress(&p, g_poh);    poh  = (uint16_t*)p;

    float* adj   = S0 + OFF_ADJ;
    float* mean1 = S0 + OFF_MEAN1;
    float* h     = S0 + OFF_H;
    float* T2    = S0 + OFF_T2;
    float* on    = S0 + OFF_ON;
    float* PP    = S0 + OFF_PP;
    float* Q     = S0 + OFF_Q;
    float* i1    = S0 + OFF_I1;
    float* i2    = S0 + OFF_I2;
    float* i3    = S0 + OFF_I3;
    float* part  = S0 + OFF_PART;

    const int SM_S128 = 2 * (2 * (128 * 80) + 2 * (128 * 80));    // 81920 (KS32)
    const int SM_S160 = 2 * (2 * (128 * 80) + 2 * (160 * 80));    // 92160 (KS32)
    const int SM_F160 = 2 * ((128 * 80) + (160 * 80));            // 46080 (KS32 fp16)
    cudaFuncSetAttribute(mma2_kernel<2,1,1,128,32>, cudaFuncAttributeMaxDynamicSharedMemorySize, SM_S128);
    cudaFuncSetAttribute(mma2_kernel<0,1,0,128,32>, cudaFuncAttributeMaxDynamicSharedMemorySize, SM_S128);
    cudaFuncSetAttribute(mma2_kernel<3,1,0,160,32>, cudaFuncAttributeMaxDynamicSharedMemorySize, SM_S160);
    cudaFuncSetAttribute(mma2_kernel<0,1,0,160,32>, cudaFuncAttributeMaxDynamicSharedMemorySize, SM_S160);
    cudaFuncSetAttribute(mma2_kernel<1,0,0,160,32>, cudaFuncAttributeMaxDynamicSharedMemorySize, SM_F160);
    cudaFuncSetAttribute(mma2_kernel<0,0,0,160,32>, cudaFuncAttributeMaxDynamicSharedMemorySize, SM_F160);

    // ---- graph: dense normalized adjacency ----
    {
        int n = NNODES * NNODES;
        zero_kernel<<<(n + 255) / 256, 256>>>(adj, n);
        edge_count_kernel<<<(NEDGES + 255) / 256, 256>>>(esrc, edst, adj);
        row_norm_kernel<<<NNODES, 256>>>(adj);
    }

    // ---- weight prep ----
    {
        int n8;
        n8 = DHID * 1024 / 8;
        splitcat8_kernel<<<(n8 + 255) / 256, 256>>>(W1l, DIN, W1r, DIN, w1h, w1l_, 1024, DHID);
        n8 = 512 * DHID / 8;
        splitcat8_kernel<<<(n8 + 255) / 256, 256>>>(W2l, DHID, nullptr, 0, w2h, w2l_, DHID, 512);
        splitcat8_kernel<<<(n8 + 255) / 256, 256>>>(W2r, DHID, nullptr, 0,
                                                    w2h + (size_t)512 * DHID,
                                                    w2l_ + (size_t)512 * DHID, DHID, 512);
        n8 = P1D * 1024 / 8;
        splitcat8_kernel<<<(n8 + 255) / 256, 256>>>(Wp1, 1024, nullptr, 0, wp1h, wp1l, 1024, P1D);
        n8 = 768 * FEATD / 8;
        splitcat8_kernel<<<(n8 + 255) / 256, 256>>>(Wi1, FEATD, nullptr, 0, wi1h, wi1l, FEATD, 768);
        n8 = 1000 * 768 / 8;
        splitcat8_kernel<<<(n8 + 255) / 256, 256>>>(Wi2, 768, nullptr, 0, wi2h, wi2l, 768, 1000);
        n8 = EMBD * 1024 / 8;
        splitcat8_kernel<<<(n8 + 255) / 256, 256>>>(Wi3, 1000, nullptr, 0, wi3h, wi3l, 1024, EMBD);
        n8 = EMBD * P1D / 8;
        tohalf8_kernel<<<(n8 + 255) / 256, 256>>>(Wp2, wp2h, n8);
    }

    // ---- mean1 = adj @ nodes  [650x512] (fp32 SIMT small) ----
    nn_small_kernel<<<dim3(DIN / 64, ceildiv(NNODES, 64)), 256>>>(
        adj, NNODES, nodes, DIN, nullptr, nullptr, 0, mean1, DIN, NNODES, DIN, NNODES);

    // ---- h = relu([mean1|nodes] @ [W1l|W1r]^T + b1)  M=650,N=4096,K=1024 ----
    mma2_kernel<2,1,1,128,32><<<dim3(DHID / 128, ceildiv(NNODES, 128)), 256, SM_S128>>>(
        mean1, DIN, nodes, DIN, DIN, nullptr, nullptr, 0,
        w1h, w1l_, 1024, h, DHID, NNODES, DHID, 1024, b1, 0, 0);

    // ---- T2 = h @ [W2l;W2r]^T  (split-K 4: 48 -> 192 CTAs) ----
    {
        size_t ps = (size_t)NNODES * 1024;
        mma2_kernel<0,1,0,128,32><<<dim3(1024 / 128, ceildiv(NNODES, 128), 4), 256, SM_S128>>>(
            h, DHID, nullptr, 0, 0, nullptr, nullptr, 0,
            w2h, w2l_, DHID, part, 1024, NNODES, 1024, DHID, nullptr, 1024, ps);
        int n = NNODES * 1024;
        reduce_parts_kernel<<<(n + 255) / 256, 256>>>(part, ps, 4, nullptr, 0,
                                                      T2, 1024, 1024, NNODES, 1024);
    }

    // ---- on = adj @ T2[:, :512] + b2 + T2[:, 512:]  [650x512] ----
    nn_small_kernel<<<dim3(DNODE / 64, ceildiv(NNODES, 64)), 256>>>(
        adj, NNODES, T2, 1024, b2, T2 + 512, 1024, on, DNODE, NNODES, DNODE, NNODES);

    // ---- PP = blockdiag(on) @ Wp1^T  (split-K 4: 48 -> 192 CTAs) ----
    {
        size_t ps = (size_t)NNODES * P1D;
        mma2_kernel<3,1,0,160,32><<<dim3(ceildiv(P1D, 160), ceildiv(NNODES, 128), 4), 256, SM_S160>>>(
            on, DNODE, nullptr, 0, DNODE, nullptr, nullptr, 0,
            wp1h, wp1l, 1024, part, P1D, NNODES, P1D, 1024, nullptr, 256, ps);
        int n = NNODES * P1D;
        reduce_parts_kernel<<<(n + 255) / 256, 256>>>(part, ps, 4, nullptr, 0,
                                                      PP, P1D, P1D, NNODES, P1D);
    }

    // ---- PP -> fp16 tables (bp1 folded into pah) ----
    {
        int n = NNODES * P1D;
        pp2half_kernel<<<(n + 255) / 256, 256>>>(PP, bp1, pah, poh);
    }

    // ---- Q = relu16(pah_i + poh_j) @ Wp2^T + bp2  (fp16, KS=32) ----
    mma2_kernel<1,0,0,160,32><<<dim3(EMBD / 160, ceildiv(NPAIRS, 128)), 256, SM_F160>>>(
        nullptr, 0, nullptr, 0, 0, pah, poh, P1D,
        wp2h, nullptr, P1D, Q, EMBD, NPAIRS, EMBD, P1D, bp2, 0, 0);

    // ---- LN rows of Q -> fp16 P ----
    ln_half_kernel<<<NPAIRS, 256>>>(Q, gp, bpn, Ph);

    // ---- image MLP (split-bf16, split-K) ----
    {
        // i1 = relu(img @ Wi1^T + bi1): K=2048, split 8 -> 96 CTAs
        size_t ps = (size_t)BATCH * 768;
        mma2_kernel<0,1,0,128,32><<<dim3(768 / 128, ceildiv(BATCH, 128), 8), 256, SM_S128>>>(
            img, FEATD, nullptr, 0, 0, nullptr, nullptr, 0,
            wi1h, wi1l, FEATD, part, 768, BATCH, 768, FEATD, nullptr, 256, ps);
        int n = BATCH * 768;
        reduce_parts_kernel<<<(n + 255) / 256, 256>>>(part, ps, 8, bi1, 1,
                                                      i1, 768, 768, BATCH, 768);
    }
    zero_kernel<<<(BATCH * 1024 + 255) / 256, 256>>>(i2, BATCH * 1024);
    {
        // i2 = relu(i1 @ Wi2^T + bi2): K=768, split 4 -> 64 CTAs
        size_t ps = (size_t)BATCH * 1024;
        mma2_kernel<0,1,0,128,32><<<dim3(ceildiv(1000, 128), ceildiv(BATCH, 128), 4), 256, SM_S128>>>(
            i1, 768, nullptr, 0, 0, nullptr, nullptr, 0,
            wi2h, wi2l, 768, part, 1024, BATCH, 1000, 768, nullptr, 192, ps);
        int n = BATCH * 1000;
        reduce_parts_kernel<<<(n + 255) / 256, 256>>>(part, ps, 4, bi2, 1,
                                                      i2, 1024, 1024, BATCH, 1000);
    }
    {
        // i3 = i2 @ Wi3^T + bi3: K=1024, split 8 -> 80 CTAs
        size_t ps = (size_t)BATCH * EMBD;
        mma2_kernel<0,1,0,160,32><<<dim3(EMBD / 160, ceildiv(BATCH, 128), 8), 256, SM_S160>>>(
            i2, 1024, nullptr, 0, 0, nullptr, nullptr, 0,
            wi3h, wi3l, 1024, part, EMBD, BATCH, EMBD, 1024, nullptr, 128, ps);
        int n = BATCH * EMBD;
        reduce_parts_kernel<<<(n + 255) / 256, 256>>>(part, ps, 8, bi3, 0,
                                                      i3, EMBD, EMBD, BATCH, EMBD);
    }
    ln_kernel<<<BATCH, 256>>>(i3, gi, bin_, EMBD);

    // ---- out = iLN @ P^T  (fp16, KS=32)  [256 x 100000] ----
    mma2_kernel<0,0,0,160,32><<<dim3(NPAIRS / 160, ceildiv(BATCH, 128)), 256, SM_F160>>>(
        i3, EMBD, nullptr, 0, 0, nullptr, nullptr, 0,
        Ph, nullptr, EMBD, out, NPAIRS, BATCH, NPAIRS, EMBD, nullptr, 0, 0);
}

// round 15
// speedup vs baseline: 1.2721x; 1.0695x over previous
#include <cuda_runtime.h>
#include <cuda_fp16.h>
#include <cuda_bf16.h>
#include <cstdint>

#define NATTRS 250
#define NOBJS  400
#define NNODES 650
#define NEDGES 100000
#define DIN    512
#define DHID   4096
#define DNODE  512
#define FEATD  2048
#define EMBD   800
#define BATCH  256
#define P1D    1200
#define NPAIRS (NATTRS * NOBJS)
#define LNEPS  1e-5f

// ---------------- scratch (single __device__ global; no allocs) ----------------
#define OFF_ADJ    0ull
#define OFF_MEAN1  (OFF_ADJ   + (size_t)NNODES * NNODES)
#define OFF_H      (OFF_MEAN1 + (size_t)NNODES * DIN)
#define OFF_T2     (OFF_H     + (size_t)NNODES * DHID)
#define OFF_ON     (OFF_T2    + (size_t)NNODES * 1024)
#define OFF_PP     (OFF_ON    + (size_t)NNODES * DNODE)
#define OFF_Q      (OFF_PP    + (size_t)NNODES * P1D)
#define OFF_I1     (OFF_Q     + (size_t)NPAIRS * EMBD)
#define OFF_I2     (OFF_I1    + (size_t)BATCH * 768)
#define OFF_I3     (OFF_I2    + (size_t)BATCH * 1024)
#define OFF_PART   (OFF_I3    + (size_t)BATCH * EMBD)
#define PART_ELEMS ((size_t)4 * NNODES * P1D)
#define SCRATCH_ELEMS (OFF_PART + PART_ELEMS)

__device__ float g_scratch[SCRATCH_ELEMS];

// split-bf16 weight buffers
__device__ uint16_t g_w1c_hi[(size_t)DHID * 1024];
__device__ uint16_t g_w1c_lo[(size_t)DHID * 1024];
__device__ uint16_t g_w2c_hi[(size_t)1024 * DHID];
__device__ uint16_t g_w2c_lo[(size_t)1024 * DHID];
__device__ uint16_t g_wp1_hi[(size_t)P1D * 1024];
__device__ uint16_t g_wp1_lo[(size_t)P1D * 1024];
__device__ uint16_t g_wi1_hi[(size_t)768 * FEATD];
__device__ uint16_t g_wi1_lo[(size_t)768 * FEATD];
__device__ uint16_t g_wi2_hi[(size_t)1000 * 768];
__device__ uint16_t g_wi2_lo[(size_t)1000 * 768];
__device__ uint16_t g_wi3_hi[(size_t)EMBD * 1024];
__device__ uint16_t g_wi3_lo[(size_t)EMBD * 1024];
// fp16 buffers
__device__ uint16_t g_wp2h[(size_t)EMBD * P1D];
__device__ uint16_t g_ph[(size_t)NPAIRS * EMBD];
__device__ uint16_t g_pah[(size_t)NATTRS * P1D];
__device__ uint16_t g_poh[(size_t)NOBJS * P1D];

// ---------------- small kernels ----------------
__global__ void zero_kernel(float* p, int n) {
    int i = blockIdx.x * blockDim.x + threadIdx.x;
    if (i < n) p[i] = 0.0f;
}

__global__ void edge_count_kernel(const int* __restrict__ src,
                                  const int* __restrict__ dst,
                                  float* __restrict__ adj) {
    int e = blockIdx.x * blockDim.x + threadIdx.x;
    if (e < NEDGES) atomicAdd(&adj[(size_t)dst[e] * NNODES + src[e]], 1.0f);
}

__global__ void row_norm_kernel(float* __restrict__ adj) {
    __shared__ float sbuf[32];
    int r = blockIdx.x;
    int tid = threadIdx.x;
    float s = 0.0f;
    float* row = adj + (size_t)r * NNODES;
    for (int c = tid; c < NNODES; c += blockDim.x) s += row[c];
    for (int o = 16; o > 0; o >>= 1) s += __shfl_down_sync(0xffffffffu, s, o);
    if ((tid & 31) == 0) sbuf[tid >> 5] = s;
    __syncthreads();
    int nw = blockDim.x >> 5;
    if (tid < 32) {
        s = (tid < nw) ? sbuf[tid] : 0.0f;
        for (int o = 16; o > 0; o >>= 1) s += __shfl_down_sync(0xffffffffu, s, o);
        if (tid == 0) sbuf[0] = s;
    }
    __syncthreads();
    float inv = 1.0f / fmaxf(sbuf[0], 1.0f);
    for (int c = tid; c < NNODES; c += blockDim.x) row[c] *= inv;
}

// vectorized split-concat (x8): out row k<K1 from X1, else X2; pad 0
__global__ void splitcat8_kernel(const float* __restrict__ X1, int K1,
                                 const float* __restrict__ X2, int K2,
                                 uint16_t* __restrict__ hi, uint16_t* __restrict__ lo,
                                 int ldo, int Nrows) {
    int g = blockIdx.x * blockDim.x + threadIdx.x;
    int total = Nrows * ldo / 8;
    if (g >= total) return;
    int base = g * 8;
    int n = base / ldo, k = base - n * ldo;
    float v[8];
    if (k + 8 <= K1) {
        const float4* s = (const float4*)(X1 + (size_t)n * K1 + k);
        float4 a = s[0], b = s[1];
        v[0]=a.x; v[1]=a.y; v[2]=a.z; v[3]=a.w; v[4]=b.x; v[5]=b.y; v[6]=b.z; v[7]=b.w;
    } else if (k >= K1 && k + 8 <= K1 + K2) {
        const float4* s = (const float4*)(X2 + (size_t)n * K2 + (k - K1));
        float4 a = s[0], b = s[1];
        v[0]=a.x; v[1]=a.y; v[2]=a.z; v[3]=a.w; v[4]=b.x; v[5]=b.y; v[6]=b.z; v[7]=b.w;
    } else {
#pragma unroll
        for (int q = 0; q < 8; q++) {
            int kk = k + q;
            v[q] = (kk < K1) ? X1[(size_t)n * K1 + kk]
                 : (kk < K1 + K2 ? X2[(size_t)n * K2 + (kk - K1)] : 0.0f);
        }
    }
    union { uint16_t b[8]; uint4 u; } Uh, Ul;
#pragma unroll
    for (int q = 0; q < 8; q++) {
        __nv_bfloat16 h = __float2bfloat16(v[q]);
        Uh.b[q] = __bfloat16_as_ushort(h);
        Ul.b[q] = __bfloat16_as_ushort(__float2bfloat16(v[q] - __bfloat162float(h)));
    }
    *(uint4*)(hi + base) = Uh.u;
    *(uint4*)(lo + base) = Ul.u;
}

__global__ void tohalf8_kernel(const float* __restrict__ x,
                               uint16_t* __restrict__ y, int n8) {
    int g = blockIdx.x * blockDim.x + threadIdx.x;
    if (g >= n8) return;
    const float4* s = (const float4*)(x + g * 8);
    float4 a = s[0], b = s[1];
    union { uint16_t h[8]; uint4 u; } U;
    U.h[0] = __half_as_ushort(__float2half_rn(a.x));
    U.h[1] = __half_as_ushort(__float2half_rn(a.y));
    U.h[2] = __half_as_ushort(__float2half_rn(a.z));
    U.h[3] = __half_as_ushort(__float2half_rn(a.w));
    U.h[4] = __half_as_ushort(__float2half_rn(b.x));
    U.h[5] = __half_as_ushort(__float2half_rn(b.y));
    U.h[6] = __half_as_ushort(__float2half_rn(b.z));
    U.h[7] = __half_as_ushort(__float2half_rn(b.w));
    *(uint4*)(y + g * 8) = U.u;
}

// PP [650x1200] -> fp16 tables (x4 vectorized): pah = fp16(PP[:250]+bp1), poh = fp16(PP[250:])
__global__ void pp2half4_kernel(const float* __restrict__ PP,
                                const float* __restrict__ bp1,
                                uint16_t* __restrict__ pah,
                                uint16_t* __restrict__ poh) {
    int g = blockIdx.x * blockDim.x + threadIdx.x;
    if (g >= NNODES * P1D / 4) return;
    int base = g * 4;
    int r = base / P1D, k = base - r * P1D;
    float4 v = *(const float4*)(PP + base);
    uint16_t* dst;
    if (r < NATTRS) {
        float4 b = *(const float4*)(bp1 + k);
        v.x += b.x; v.y += b.y; v.z += b.z; v.w += b.w;
        dst = pah + (size_t)r * P1D + k;
    } else {
        dst = poh + (size_t)(r - NATTRS) * P1D + k;
    }
    __half2 h0 = __floats2half2_rn(v.x, v.y);
    __half2 h1 = __floats2half2_rn(v.z, v.w);
    *(uint32_t*)(dst)     = *(uint32_t*)&h0;
    *(uint32_t*)(dst + 2) = *(uint32_t*)&h1;
}

// vectorized in-place LayerNorm over D=800 (fp32), one row per block
__global__ void ln_kernel(float* __restrict__ X,
                          const float* __restrict__ g,
                          const float* __restrict__ b, int D) {
    __shared__ float sA[32], sB[32];
    int r = blockIdx.x;
    int tid = threadIdx.x;
    float* x = X + (size_t)r * D;
    const int nv = D / 4;
    float4 v = make_float4(0.f, 0.f, 0.f, 0.f);
    float s = 0.0f, s2 = 0.0f;
    if (tid < nv) {
        v = ((const float4*)x)[tid];
        s = v.x + v.y + v.z + v.w;
        s2 = v.x * v.x + v.y * v.y + v.z * v.z + v.w * v.w;
    }
    for (int o = 16; o > 0; o >>= 1) {
        s += __shfl_down_sync(0xffffffffu, s, o);
        s2 += __shfl_down_sync(0xffffffffu, s2, o);
    }
    if ((tid & 31) == 0) { sA[tid >> 5] = s; sB[tid >> 5] = s2; }
    __syncthreads();
    int nw = blockDim.x >> 5;
    if (tid < 32) {
        s = (tid < nw) ? sA[tid] : 0.0f;
        s2 = (tid < nw) ? sB[tid] : 0.0f;
        for (int o = 16; o > 0; o >>= 1) {
            s += __shfl_down_sync(0xffffffffu, s, o);
            s2 += __shfl_down_sync(0xffffffffu, s2, o);
        }
        if (tid == 0) { sA[0] = s; sB[0] = s2; }
    }
    __syncthreads();
    float invD = 1.0f / (float)D;
    float m = sA[0] * invD;
    float var = fmaxf(sB[0] * invD - m * m, 0.0f);
    float inv = rsqrtf(var + LNEPS);
    if (tid < nv) {
        float4 gg = ((const float4*)g)[tid];
        float4 bb = ((const float4*)b)[tid];
        float4 o;
        o.x = (v.x - m) * inv * gg.x + bb.x;
        o.y = (v.y - m) * inv * gg.y + bb.y;
        o.z = (v.z - m) * inv * gg.z + bb.z;
        o.w = (v.w - m) * inv * gg.w + bb.w;
        ((float4*)x)[tid] = o;
    }
}

// vectorized LayerNorm of Q rows -> fp16 P, one row per block (EMBD=800)
__global__ void ln_half_kernel(const float* __restrict__ Q,
                               const float* __restrict__ g,
                               const float* __restrict__ b,
                               uint16_t* __restrict__ Ph) {
    __shared__ float sA[32], sB[32];
    int r = blockIdx.x;
    int tid = threadIdx.x;
    const float* x = Q + (size_t)r * EMBD;
    const int nv = EMBD / 4;   // 200
    float4 v = make_float4(0.f, 0.f, 0.f, 0.f);
    float s = 0.0f, s2 = 0.0f;
    if (tid < nv) {
        v = ((const float4*)x)[tid];
        s = v.x + v.y + v.z + v.w;
        s2 = v.x * v.x + v.y * v.y + v.z * v.z + v.w * v.w;
    }
    for (int o = 16; o > 0; o >>= 1) {
        s += __shfl_down_sync(0xffffffffu, s, o);
        s2 += __shfl_down_sync(0xffffffffu, s2, o);
    }
    if ((tid & 31) == 0) { sA[tid >> 5] = s; sB[tid >> 5] = s2; }
    __syncthreads();
    int nw = blockDim.x >> 5;
    if (tid < 32) {
        s = (tid < nw) ? sA[tid] : 0.0f;
        s2 = (tid < nw) ? sB[tid] : 0.0f;
        for (int o = 16; o > 0; o >>= 1) {
            s += __shfl_down_sync(0xffffffffu, s, o);
            s2 += __shfl_down_sync(0xffffffffu, s2, o);
        }
        if (tid == 0) { sA[0] = s; sB[0] = s2; }
    }
    __syncthreads();
    float invD = 1.0f / (float)EMBD;
    float m = sA[0] * invD;
    float var = fmaxf(sB[0] * invD - m * m, 0.0f);
    float inv = rsqrtf(var + LNEPS);
    if (tid < nv) {
        float4 gg = ((const float4*)g)[tid];
        float4 bb = ((const float4*)b)[tid];
        float p0 = (v.x - m) * inv * gg.x + bb.x;
        float p1 = (v.y - m) * inv * gg.y + bb.y;
        float p2 = (v.z - m) * inv * gg.z + bb.z;
        float p3 = (v.w - m) * inv * gg.w + bb.w;
        __half2 h0 = __floats2half2_rn(p0, p1);
        __half2 h1 = __floats2half2_rn(p2, p3);
        uint16_t* dst = Ph + (size_t)r * EMBD + tid * 4;
        *(uint32_t*)(dst)     = *(uint32_t*)&h0;
        *(uint32_t*)(dst + 2) = *(uint32_t*)&h1;
    }
}

// sum split-K partials + bias (+relu) -> C
__global__ void reduce_parts_kernel(const float* __restrict__ part, size_t pstride,
                                    int nz, const float* __restrict__ bias, int relu,
                                    float* __restrict__ C, int ldc, int ldp,
                                    int M, int NB) {
    int i = blockIdx.x * blockDim.x + threadIdx.x;
    if (i >= M * NB) return;
    int m = i / NB, n = i - m * NB;
    float s = 0.0f;
    for (int z = 0; z < nz; z++)
        s += part[(size_t)z * pstride + (size_t)m * ldp + n];
    if (bias) s += bias[n];
    if (relu) s = fmaxf(s, 0.0f);
    C[(size_t)m * ldc + n] = s;
}

// ---------------- small fp32 NN gemm (64x64 tiles) ----------------
__global__ __launch_bounds__(256)
void nn_small_kernel(const float* __restrict__ A, int lda,
                     const float* __restrict__ B, int ldb,
                     const float* __restrict__ bias,
                     const float* __restrict__ extra, int lde,
                     float* __restrict__ C, int ldc,
                     int M, int N, int K) {
    __shared__ float As[16][68];
    __shared__ float Bs[16][68];
    int tid = threadIdx.x;
    int bm = blockIdx.y * 64, bn = blockIdx.x * 64;
    int tx = tid & 15, ty = tid >> 4;
    float acc[4][4];
#pragma unroll
    for (int i = 0; i < 4; i++)
#pragma unroll
        for (int j = 0; j < 4; j++) acc[i][j] = 0.0f;
    for (int k0 = 0; k0 < K; k0 += 16) {
        for (int e = tid; e < 1024; e += 256) {
            int row = e & 63, kk = e >> 6;
            int gm = bm + row, gk = k0 + kk, gn = bn + row;
            As[kk][row] = (gm < M && gk < K) ? A[(size_t)gm * lda + gk] : 0.0f;
            Bs[kk][row] = (gn < N && gk < K) ? B[(size_t)gk * ldb + gn] : 0.0f;
        }
        __syncthreads();
#pragma unroll
        for (int kk = 0; kk < 16; kk++) {
            float a[4], b[4];
#pragma unroll
            for (int i = 0; i < 4; i++) a[i] = As[kk][ty * 4 + i];
#pragma unroll
            for (int j = 0; j < 4; j++) b[j] = Bs[kk][tx * 4 + j];
#pragma unroll
            for (int i = 0; i < 4; i++)
#pragma unroll
                for (int j = 0; j < 4; j++) acc[i][j] += a[i] * b[j];
        }
        __syncthreads();
    }
#pragma unroll
    for (int i = 0; i < 4; i++) {
        int m = bm + ty * 4 + i;
        if (m >= M) continue;
#pragma unroll
        for (int j = 0; j < 4; j++) {
            int n = bn + tx * 4 + j;
            if (n >= N) continue;
            float v = acc[i][j];
            if (bias) v += bias[n];
            if (extra) v += extra[(size_t)m * lde + n];
            C[(size_t)m * ldc + n] = v;
        }
    }
}

// ================= generalized tensor-core GEMM =================
// (unchanged from R13: split-K capable, SPLIT bf16 3-term / fp16 1-term)

__device__ __forceinline__ uint32_t smem_u32(const void* p) {
    return (uint32_t)__cvta_generic_to_shared(p);
}
__device__ __forceinline__ void ldmA4(uint32_t r[4], uint32_t addr) {
    asm volatile("ldmatrix.sync.aligned.m8n8.x4.shared.b16 {%0,%1,%2,%3},[%4];\n"
                 : "=r"(r[0]), "=r"(r[1]), "=r"(r[2]), "=r"(r[3]) : "r"(addr));
}
__device__ __forceinline__ void ldmB2(uint32_t r[2], uint32_t addr) {
    asm volatile("ldmatrix.sync.aligned.m8n8.x2.shared.b16 {%0,%1},[%2];\n"
                 : "=r"(r[0]), "=r"(r[1]) : "r"(addr));
}
__device__ __forceinline__ void ldmB4(uint32_t r0[2], uint32_t r1[2], uint32_t addr) {
    asm volatile("ldmatrix.sync.aligned.m8n8.x4.shared.b16 {%0,%1,%2,%3},[%4];\n"
                 : "=r"(r0[0]), "=r"(r0[1]), "=r"(r1[0]), "=r"(r1[1]) : "r"(addr));
}
__device__ __forceinline__ void mma_f16(float d[4], const uint32_t a[4],
                                        const uint32_t b[2]) {
    asm volatile(
        "mma.sync.aligned.m16n8k16.row.col.f32.f16.f16.f32 "
        "{%0,%1,%2,%3},{%4,%5,%6,%7},{%8,%9},{%0,%1,%2,%3};\n"
        : "+f"(d[0]), "+f"(d[1]), "+f"(d[2]), "+f"(d[3])
        : "r"(a[0]), "r"(a[1]), "r"(a[2]), "r"(a[3]), "r"(b[0]), "r"(b[1]));
}
__device__ __forceinline__ void mma_bf16(float d[4], const uint32_t a[4],
                                         const uint32_t b[2]) {
    asm volatile(
        "mma.sync.aligned.m16n8k16.row.col.f32.bf16.bf16.f32 "
        "{%0,%1,%2,%3},{%4,%5,%6,%7},{%8,%9},{%0,%1,%2,%3};\n"
        : "+f"(d[0]), "+f"(d[1]), "+f"(d[2]), "+f"(d[3])
        : "r"(a[0]), "r"(a[1]), "r"(a[2]), "r"(a[3]), "r"(b[0]), "r"(b[1]));
}
__device__ __forceinline__ void cp16(uint32_t dst, const void* src) {
    asm volatile("cp.async.cg.shared.global [%0], [%1], 16;\n" :: "r"(dst), "l"(src));
}
__device__ __forceinline__ void cp_commit() { asm volatile("cp.async.commit_group;\n"); }
__device__ __forceinline__ void cp_wait0()  { asm volatile("cp.async.wait_group 0;\n"); }

__device__ __forceinline__ uint32_t h2addrelu(uint32_t a, uint32_t b) {
    __half2 ha = *(__half2*)&a;
    __half2 hb = *(__half2*)&b;
    __half2 r = __hmax2(__hadd2(ha, hb), __float2half2_rn(0.0f));
    return *(uint32_t*)&r;
}
__device__ __forceinline__ uint4 h2addrelu4(uint4 a, uint4 b) {
    uint4 r;
    r.x = h2addrelu(a.x, b.x); r.y = h2addrelu(a.y, b.y);
    r.z = h2addrelu(a.z, b.z); r.w = h2addrelu(a.w, b.w);
    return r;
}

template <int AMODE, int SPLIT, int RELU, int NT_, int KS_>
__global__ __launch_bounds__(256)
void mma2_kernel(const float* __restrict__ A1, int lda1,
                 const float* __restrict__ A2, int lda2, int K1,
                 const uint16_t* __restrict__ H1,
                 const uint16_t* __restrict__ H2, int ldh,
                 const uint16_t* __restrict__ Bhi,
                 const uint16_t* __restrict__ Blo, int ldb,
                 float* __restrict__ C, int ldc,
                 int M, int NB, int K,
                 const float* __restrict__ bias,
                 int kchunk, size_t pstride) {
    constexpr int NI   = NT_ / 32;
    constexpr int RB   = (KS_ + 8) * 2;
    constexpr int ASZ  = 128 * RB;
    constexpr int BSZ  = NT_ * RB;
    constexpr int NPLA = SPLIT ? 2 : 1;
    constexpr int STRIDE = NPLA * (ASZ + BSZ);
    constexpr int AhiO = 0;
    constexpr int AloO = ASZ;
    constexpr int BhiO = NPLA * ASZ;
    constexpr int BloO = NPLA * ASZ + BSZ;
    constexpr int NSUB = KS_ / 16;
    constexpr int GH   = KS_ / 16;

    extern __shared__ char smem[];
    const uint32_t sb = smem_u32(smem);
    const int tid = threadIdx.x;
    const int warp = tid >> 5;
    const int lane = tid & 31;
    const int bm = blockIdx.y * 128;
    const int bn = blockIdx.x * NT_;
    const int wm = warp & 1;
    const int wn = warp >> 1;

    int koff = 0, kend = K;
    if (kchunk > 0) {
        koff = blockIdx.z * kchunk;
        int ke = koff + kchunk;
        kend = ke < K ? ke : K;
        C += (size_t)blockIdx.z * pstride;
    }

    const int ar = tid >> 1;
    const int ah = (tid & 1) * (KS_ / 2);
    const int arow = bm + ar;
    const bool avalid = arow < M;
    const float* pA = nullptr;
    const float* pA2 = nullptr;
    const uint16_t* pH1 = nullptr;
    const uint16_t* pH2 = nullptr;
    bool attr_row = true;
    if (AMODE == 0) {
        pA = A1 + (size_t)(avalid ? arow : 0) * lda1;
    } else if (AMODE == 1) {
        int ai = avalid ? (arow / NOBJS) : 0;
        int oi = avalid ? (arow - ai * NOBJS) : 0;
        pH1 = H1 + (size_t)ai * ldh;
        pH2 = H2 + (size_t)oi * ldh;
    } else if (AMODE == 2) {
        pA = A1 + (size_t)(avalid ? arow : 0) * lda1;
        pA2 = A2 + (size_t)(avalid ? arow : 0) * lda2;
    } else {
        pA = A1 + (size_t)(avalid ? arow : 0) * lda1;
        attr_row = arow < NATTRS;
    }

    float acc[4][NI][4];
#pragma unroll
    for (int i = 0; i < 4; i++)
#pragma unroll
        for (int j = 0; j < NI; j++)
#pragma unroll
            for (int c = 0; c < 4; c++) acc[i][j][c] = 0.0f;

    float va[KS_ / 2];
    uint4 vh[GH];
    auto load_A = [&](int kb) {
        int k0 = kb + ah;
        if (AMODE == 1) {
#pragma unroll
            for (int g = 0; g < GH; g++) {
                int kg = k0 + g * 8;
                if (avalid && kg < kend) {
                    vh[g] = h2addrelu4(*(const uint4*)(pH1 + kg),
                                       *(const uint4*)(pH2 + kg));
                } else {
                    vh[g] = make_uint4(0, 0, 0, 0);
                }
            }
            return;
        }
#pragma unroll
        for (int q = 0; q < KS_ / 2; q++) va[q] = 0.0f;
#pragma unroll
        for (int g = 0; g < KS_ / 8; g++) {
            int kg = k0 + g * 4;
            if (!avalid || kg >= kend) continue;
            const float* src = nullptr;
            if (AMODE == 0) {
                src = pA + kg;
            } else if (AMODE == 2) {
                src = (kg < K1) ? (pA + kg) : (pA2 + (kg - K1));
            } else {
                bool use = attr_row ? (kg < K1) : (kg >= K1);
                if (!use) continue;
                src = attr_row ? (pA + kg) : (pA + (kg - K1));
            }
            float4 x = *(const float4*)(src);
            va[g*4+0] = x.x; va[g*4+1] = x.y; va[g*4+2] = x.z; va[g*4+3] = x.w;
        }
    };
    auto sts_A = [&](int buf) {
        const int base = buf * STRIDE;
        uint32_t off = (uint32_t)(ar * RB + ah * 2);
        if (AMODE == 1) {
#pragma unroll
            for (int g = 0; g < GH; g++)
                *(uint4*)(smem + base + AhiO + off + g * 16) = vh[g];
            return;
        }
#pragma unroll
        for (int g = 0; g < GH; g++) {
            union { uint16_t b[8]; uint4 u; } Uh, Ul;
#pragma unroll
            for (int q = 0; q < 8; q++) {
                float v = va[g * 8 + q];
                if (SPLIT) {
                    __nv_bfloat16 h = __float2bfloat16(v);
                    Uh.b[q] = __bfloat16_as_ushort(h);
                    Ul.b[q] = __bfloat16_as_ushort(__float2bfloat16(v - __bfloat162float(h)));
                } else {
                    Uh.b[q] = __half_as_ushort(__float2half_rn(v));
                }
            }
            *(uint4*)(smem + base + AhiO + off + g * 16) = Uh.u;
            if (SPLIT) *(uint4*)(smem + base + AloO + off + g * 16) = Ul.u;
        }
    };
    auto load_B = [&](int kb, int buf) {
        const int base = buf * STRIDE;
        constexpr int CPR = KS_ / 8;
        const int total = NT_ * CPR * NPLA;
        for (int i = tid; i < total; i += 256) {
            int plane = (i >= NT_ * CPR) ? 1 : 0;
            int v = i - plane * NT_ * CPR;
            int row = v / CPR;
            int c = v - row * CPR;
            int k0 = kb + c * 8;
            uint32_t doff = (uint32_t)(base + (plane ? BloO : BhiO) + row * RB + c * 16);
            if ((bn + row) < NB && k0 < kend) {
                const uint16_t* src = (plane ? Blo : Bhi) + (size_t)(bn + row) * ldb + k0;
                cp16(sb + doff, src);
            } else {
                *(uint4*)(smem + doff) = make_uint4(0u, 0u, 0u, 0u);
            }
        }
    };

    const int NST = (kend - koff + KS_ - 1) / KS_;
    load_A(koff);
    sts_A(0);
    load_B(koff, 0);
    cp_commit();
    cp_wait0();
    __syncthreads();

    const int arowf = lane & 15;
    const int akf = ((lane >> 4) & 1) * 8;
    const int brow = lane & 7;
    const int bkf = ((lane >> 3) & 1) * 8;
    const int browx = (lane & 7) + ((lane & 16) >> 1);
    const int bkx = (lane & 8);

    for (int st = 0; st < NST; st++) {
        const int cur = st & 1;
        const int nxt = cur ^ 1;
        const bool hasnext = (st + 1) < NST;
        if (hasnext) {
            load_A(koff + (st + 1) * KS_);
            load_B(koff + (st + 1) * KS_, nxt);
            cp_commit();
        }
        const int cbase = cur * STRIDE;
#pragma unroll
        for (int sub = 0; sub < NSUB; sub++) {
            if (koff + st * KS_ + sub * 16 >= kend) break;
            const int kcol = (sub * 16 + akf) * 2;
            const int kcolb = (sub * 16 + bkf) * 2;
            const int kcolx = (sub * 16 + bkx) * 2;
            uint32_t afh[4][4], afl[4][4];
#pragma unroll
            for (int mi = 0; mi < 4; mi++) {
                int m0 = wm * 64 + mi * 16;
                ldmA4(afh[mi], sb + cbase + AhiO + (m0 + arowf) * RB + kcol);
                if (SPLIT)
                    ldmA4(afl[mi], sb + cbase + AloO + (m0 + arowf) * RB + kcol);
            }
            uint32_t bfh[NI][2], bfl[NI][2];
#pragma unroll
            for (int ni = 0; ni + 1 < NI; ni += 2) {
                int n0 = wn * (NT_ / 4) + ni * 8;
                ldmB4(bfh[ni], bfh[ni + 1],
                      sb + cbase + BhiO + (n0 + browx) * RB + kcolx);
                if (SPLIT)
                    ldmB4(bfl[ni], bfl[ni + 1],
                          sb + cbase + BloO + (n0 + browx) * RB + kcolx);
            }
            if (NI & 1) {
                constexpr int ni = NI - 1;
                int n0 = wn * (NT_ / 4) + ni * 8;
                ldmB2(bfh[ni], sb + cbase + BhiO + (n0 + brow) * RB + kcolb);
                if (SPLIT)
                    ldmB2(bfl[ni], sb + cbase + BloO + (n0 + brow) * RB + kcolb);
            }
#pragma unroll
            for (int mi = 0; mi < 4; mi++)
#pragma unroll
                for (int ni = 0; ni < NI; ni++) {
                    if (SPLIT) {
                        mma_bf16(acc[mi][ni], afh[mi], bfh[ni]);
                        mma_bf16(acc[mi][ni], afh[mi], bfl[ni]);
                        mma_bf16(acc[mi][ni], afl[mi], bfh[ni]);
                    } else {
                        mma_f16(acc[mi][ni], afh[mi], bfh[ni]);
                    }
                }
        }
        if (hasnext) sts_A(nxt);
        cp_wait0();
        __syncthreads();
    }

    // epilogue
#pragma unroll
    for (int mi = 0; mi < 4; mi++) {
#pragma unroll
        for (int ni = 0; ni < NI; ni++) {
            int m0 = bm + wm * 64 + mi * 16 + (lane >> 2);
            int n0 = bn + wn * (NT_ / 4) + ni * 8 + (lane & 3) * 2;
            if (n0 >= NB) continue;
            float b0 = bias ? bias[n0] : 0.0f;
            float b1v = bias ? bias[n0 + 1] : 0.0f;
            float v0 = acc[mi][ni][0] + b0, v1 = acc[mi][ni][1] + b1v;
            float v2 = acc[mi][ni][2] + b0, v3 = acc[mi][ni][3] + b1v;
            if (RELU) {
                v0 = fmaxf(v0, 0.0f); v1 = fmaxf(v1, 0.0f);
                v2 = fmaxf(v2, 0.0f); v3 = fmaxf(v3, 0.0f);
            }
            if (m0 < M) *(float2*)(C + (size_t)m0 * ldc + n0) = make_float2(v0, v1);
            if (m0 + 8 < M) *(float2*)(C + (size_t)(m0 + 8) * ldc + n0) = make_float2(v2, v3);
        }
    }
}

// ---------------- host ----------------
static inline int ceildiv(int a, int b) { return (a + b - 1) / b; }

extern "C" void kernel_launch(void* const* d_in, const int* in_sizes, int n_in,
                              void* d_out, int out_size) {
    const float* img   = (const float*)d_in[0];
    const float* nodes = (const float*)d_in[1];
    const int*   esrc  = (const int*)d_in[2];
    const int*   edst  = (const int*)d_in[3];
    const float* W1l   = (const float*)d_in[4];
    const float* b1    = (const float*)d_in[5];
    const float* W1r   = (const float*)d_in[6];
    const float* W2l   = (const float*)d_in[7];
    const float* b2    = (const float*)d_in[8];
    const float* W2r   = (const float*)d_in[9];
    const float* Wp1   = (const float*)d_in[10];
    const float* bp1   = (const float*)d_in[11];
    const float* Wp2   = (const float*)d_in[12];
    const float* bp2   = (const float*)d_in[13];
    const float* gp    = (const float*)d_in[14];
    const float* bpn   = (const float*)d_in[15];
    const float* Wi1   = (const float*)d_in[16];
    const float* bi1   = (const float*)d_in[17];
    const float* Wi2   = (const float*)d_in[18];
    const float* bi2   = (const float*)d_in[19];
    const float* Wi3   = (const float*)d_in[20];
    const float* bi3   = (const float*)d_in[21];
    const float* gi    = (const float*)d_in[22];
    const float* bin_  = (const float*)d_in[23];
    float* out = (float*)d_out;

    void* p;
    cudaGetSymbolAddress(&p, g_scratch);
    float* S0 = (float*)p;
    uint16_t *w1h, *w1l_, *w2h, *w2l_, *wp1h, *wp1l, *wi1h, *wi1l,
             *wi2h, *wi2l, *wi3h, *wi3l, *wp2h, *Ph, *pah, *poh;
    cudaGetSymbolAddress(&p, g_w1c_hi); w1h  = (uint16_t*)p;
    cudaGetSymbolAddress(&p, g_w1c_lo); w1l_ = (uint16_t*)p;
    cudaGetSymbolAddress(&p, g_w2c_hi); w2h  = (uint16_t*)p;
    cudaGetSymbolAddress(&p, g_w2c_lo); w2l_ = (uint16_t*)p;
    cudaGetSymbolAddress(&p, g_wp1_hi); wp1h = (uint16_t*)p;
    cudaGetSymbolAddress(&p, g_wp1_lo); wp1l = (uint16_t*)p;
    cudaGetSymbolAddress(&p, g_wi1_hi); wi1h = (uint16_t*)p;
    cudaGetSymbolAddress(&p, g_wi1_lo); wi1l = (uint16_t*)p;
    cudaGetSymbolAddress(&p, g_wi2_hi); wi2h = (uint16_t*)p;
    cudaGetSymbolAddress(&p, g_wi2_lo); wi2l = (uint16_t*)p;
    cudaGetSymbolAddress(&p, g_wi3_hi); wi3h = (uint16_t*)p;
    cudaGetSymbolAddress(&p, g_wi3_lo); wi3l = (uint16_t*)p;
    cudaGetSymbolAddress(&p, g_wp2h);   wp2h = (uint16_t*)p;
    cudaGetSymbolAddress(&p, g_ph);     Ph   = (uint16_t*)p;
    cudaGetSymbolAddress(&p, g_pah);    pah  = (uint16_t*)p;
    cudaGetSymbolAddress(&p, g_poh);    poh  = (uint16_t*)p;

    float* adj   = S0 + OFF_ADJ;
    float* mean1 = S0 + OFF_MEAN1;
    float* h     = S0 + OFF_H;
    float* T2    = S0 + OFF_T2;
    float* on    = S0 + OFF_ON;
    float* PP    = S0 + OFF_PP;
    float* Q     = S0 + OFF_Q;
    float* i1    = S0 + OFF_I1;
    float* i2    = S0 + OFF_I2;
    float* i3    = S0 + OFF_I3;
    float* part  = S0 + OFF_PART;

    const int SM_S128 = 2 * (2 * (128 * 80) + 2 * (128 * 80));
    const int SM_S160 = 2 * (2 * (128 * 80) + 2 * (160 * 80));
    const int SM_F160 = 2 * ((128 * 80) + (160 * 80));
    cudaFuncSetAttribute(mma2_kernel<2,1,1,128,32>, cudaFuncAttributeMaxDynamicSharedMemorySize, SM_S128);
    cudaFuncSetAttribute(mma2_kernel<0,1,0,128,32>, cudaFuncAttributeMaxDynamicSharedMemorySize, SM_S128);
    cudaFuncSetAttribute(mma2_kernel<3,1,0,160,32>, cudaFuncAttributeMaxDynamicSharedMemorySize, SM_S160);
    cudaFuncSetAttribute(mma2_kernel<0,1,0,160,32>, cudaFuncAttributeMaxDynamicSharedMemorySize, SM_S160);
    cudaFuncSetAttribute(mma2_kernel<1,0,0,160,32>, cudaFuncAttributeMaxDynamicSharedMemorySize, SM_F160);
    cudaFuncSetAttribute(mma2_kernel<0,0,0,160,32>, cudaFuncAttributeMaxDynamicSharedMemorySize, SM_F160);

    // ---- graph: dense normalized adjacency ----
    {
        int n = NNODES * NNODES;
        zero_kernel<<<(n + 255) / 256, 256>>>(adj, n);
        edge_count_kernel<<<(NEDGES + 255) / 256, 256>>>(esrc, edst, adj);
        row_norm_kernel<<<NNODES, 256>>>(adj);
    }

    // ---- weight prep ----
    {
        int n8;
        n8 = DHID * 1024 / 8;
        splitcat8_kernel<<<(n8 + 255) / 256, 256>>>(W1l, DIN, W1r, DIN, w1h, w1l_, 1024, DHID);
        n8 = 512 * DHID / 8;
        splitcat8_kernel<<<(n8 + 255) / 256, 256>>>(W2l, DHID, nullptr, 0, w2h, w2l_, DHID, 512);
        splitcat8_kernel<<<(n8 + 255) / 256, 256>>>(W2r, DHID, nullptr, 0,
                                                    w2h + (size_t)512 * DHID,
                                                    w2l_ + (size_t)512 * DHID, DHID, 512);
        n8 = P1D * 1024 / 8;
        splitcat8_kernel<<<(n8 + 255) / 256, 256>>>(Wp1, 1024, nullptr, 0, wp1h, wp1l, 1024, P1D);
        n8 = 768 * FEATD / 8;
        splitcat8_kernel<<<(n8 + 255) / 256, 256>>>(Wi1, FEATD, nullptr, 0, wi1h, wi1l, FEATD, 768);
        n8 = 1000 * 768 / 8;
        splitcat8_kernel<<<(n8 + 255) / 256, 256>>>(Wi2, 768, nullptr, 0, wi2h, wi2l, 768, 1000);
        n8 = EMBD * 1024 / 8;
        splitcat8_kernel<<<(n8 + 255) / 256, 256>>>(Wi3, 1000, nullptr, 0, wi3h, wi3l, 1024, EMBD);
        n8 = EMBD * P1D / 8;
        tohalf8_kernel<<<(n8 + 255) / 256, 256>>>(Wp2, wp2h, n8);
    }

    // ---- mean1 = adj @ nodes  [650x512] (fp32 SIMT small) ----
    nn_small_kernel<<<dim3(DIN / 64, ceildiv(NNODES, 64)), 256>>>(
        adj, NNODES, nodes, DIN, nullptr, nullptr, 0, mean1, DIN, NNODES, DIN, NNODES);

    // ---- h = relu([mean1|nodes] @ [W1l|W1r]^T + b1)  M=650,N=4096,K=1024 ----
    mma2_kernel<2,1,1,128,32><<<dim3(DHID / 128, ceildiv(NNODES, 128)), 256, SM_S128>>>(
        mean1, DIN, nodes, DIN, DIN, nullptr, nullptr, 0,
        w1h, w1l_, 1024, h, DHID, NNODES, DHID, 1024, b1, 0, 0);

    // ---- T2 = h @ [W2l;W2r]^T  (split-K 4) ----
    {
        size_t ps = (size_t)NNODES * 1024;
        mma2_kernel<0,1,0,128,32><<<dim3(1024 / 128, ceildiv(NNODES, 128), 4), 256, SM_S128>>>(
            h, DHID, nullptr, 0, 0, nullptr, nullptr, 0,
            w2h, w2l_, DHID, part, 1024, NNODES, 1024, DHID, nullptr, 1024, ps);
        int n = NNODES * 1024;
        reduce_parts_kernel<<<(n + 255) / 256, 256>>>(part, ps, 4, nullptr, 0,
                                                      T2, 1024, 1024, NNODES, 1024);
    }

    // ---- on = adj @ T2[:, :512] + b2 + T2[:, 512:]  [650x512] ----
    nn_small_kernel<<<dim3(DNODE / 64, ceildiv(NNODES, 64)), 256>>>(
        adj, NNODES, T2, 1024, b2, T2 + 512, 1024, on, DNODE, NNODES, DNODE, NNODES);

    // ---- PP = blockdiag(on) @ Wp1^T  (split-K 4) ----
    {
        size_t ps = (size_t)NNODES * P1D;
        mma2_kernel<3,1,0,160,32><<<dim3(ceildiv(P1D, 160), ceildiv(NNODES, 128), 4), 256, SM_S160>>>(
            on, DNODE, nullptr, 0, DNODE, nullptr, nullptr, 0,
            wp1h, wp1l, 1024, part, P1D, NNODES, P1D, 1024, nullptr, 256, ps);
        int n = NNODES * P1D;
        reduce_parts_kernel<<<(n + 255) / 256, 256>>>(part, ps, 4, nullptr, 0,
                                                      PP, P1D, P1D, NNODES, P1D);
    }

    // ---- PP -> fp16 tables (vectorized, bp1 folded into pah) ----
    {
        int n4 = NNODES * P1D / 4;
        pp2half4_kernel<<<(n4 + 255) / 256, 256>>>(PP, bp1, pah, poh);
    }

    // ---- Q = relu16(pah_i + poh_j) @ Wp2^T + bp2  (fp16, KS=32) ----
    mma2_kernel<1,0,0,160,32><<<dim3(EMBD / 160, ceildiv(NPAIRS, 128)), 256, SM_F160>>>(
        nullptr, 0, nullptr, 0, 0, pah, poh, P1D,
        wp2h, nullptr, P1D, Q, EMBD, NPAIRS, EMBD, P1D, bp2, 0, 0);

    // ---- LN rows of Q -> fp16 P (vectorized) ----
    ln_half_kernel<<<NPAIRS, 256>>>(Q, gp, bpn, Ph);

    // ---- image MLP (split-bf16, split-K) ----
    {
        size_t ps = (size_t)BATCH * 768;
        mma2_kernel<0,1,0,128,32><<<dim3(768 / 128, ceildiv(BATCH, 128), 8), 256, SM_S128>>>(
            img, FEATD, nullptr, 0, 0, nullptr, nullptr, 0,
            wi1h, wi1l, FEATD, part, 768, BATCH, 768, FEATD, nullptr, 256, ps);
        int n = BATCH * 768;
        reduce_parts_kernel<<<(n + 255) / 256, 256>>>(part, ps, 8, bi1, 1,
                                                      i1, 768, 768, BATCH, 768);
    }
    zero_kernel<<<(BATCH * 1024 + 255) / 256, 256>>>(i2, BATCH * 1024);
    {
        size_t ps = (size_t)BATCH * 1024;
        mma2_kernel<0,1,0,128,32><<<dim3(ceildiv(1000, 128), ceildiv(BATCH, 128), 4), 256, SM_S128>>>(
            i1, 768, nullptr, 0, 0, nullptr, nullptr, 0,
            wi2h, wi2l, 768, part, 1024, BATCH, 1000, 768, nullptr, 192, ps);
        int n = BATCH * 1000;
        reduce_parts_kernel<<<(n + 255) / 256, 256>>>(part, ps, 4, bi2, 1,
                                                      i2, 1024, 1024, BATCH, 1000);
    }
    {
        size_t ps = (size_t)BATCH * EMBD;
        mma2_kernel<0,1,0,160,32><<<dim3(EMBD / 160, ceildiv(BATCH, 128), 8), 256, SM_S160>>>(
            i2, 1024, nullptr, 0, 0, nullptr, nullptr, 0,
            wi3h, wi3l, 1024, part, EMBD, BATCH, EMBD, 1024, nullptr, 128, ps);
        int n = BATCH * EMBD;
        reduce_parts_kernel<<<(n + 255) / 256, 256>>>(part, ps, 8, bi3, 0,
                                                      i3, EMBD, EMBD, BATCH, EMBD);
    }
    ln_kernel<<<BATCH, 256>>>(i3, gi, bin_, EMBD);

    // ---- out = iLN @ P^T  (fp16, KS=32)  [256 x 100000] ----
    mma2_kernel<0,0,0,160,32><<<dim3(NPAIRS / 160, ceildiv(BATCH, 128)), 256, SM_F160>>>(
        i3, EMBD, nullptr, 0, 0, nullptr, nullptr, 0,
        Ph, nullptr, EMBD, out, NPAIRS, BATCH, NPAIRS, EMBD, nullptr, 0, 0);
}

// round 17
// speedup vs baseline: 1.3974x; 1.0985x over previous
#include <cuda_runtime.h>
#include <cuda_fp16.h>
#include <cuda_bf16.h>
#include <cstdint>

#define NATTRS 250
#define NOBJS  400
#define NNODES 650
#define NEDGES 100000
#define DIN    512
#define DHID   4096
#define DNODE  512
#define FEATD  2048
#define EMBD   800
#define BATCH  256
#define P1D    1200
#define NPAIRS (NATTRS * NOBJS)
#define LNEPS  1e-5f

// ---------------- scratch (single __device__ global; no allocs) ----------------
#define OFF_ADJ    0ull
#define OFF_MEAN1  (OFF_ADJ   + (size_t)NNODES * NNODES)
#define OFF_H      (OFF_MEAN1 + (size_t)NNODES * DIN)
#define OFF_T2     (OFF_H     + (size_t)NNODES * DHID)
#define OFF_ON     (OFF_T2    + (size_t)NNODES * 1024)
#define OFF_PP     (OFF_ON    + (size_t)NNODES * DNODE)
#define OFF_Q      (OFF_PP    + (size_t)NNODES * P1D)
#define OFF_I1     (OFF_Q     + (size_t)NPAIRS * EMBD)
#define OFF_I2     (OFF_I1    + (size_t)BATCH * 768)
#define OFF_I3     (OFF_I2    + (size_t)BATCH * 1024)
#define OFF_PART   (OFF_I3    + (size_t)BATCH * EMBD)
#define PART_ELEMS ((size_t)4 * NNODES * P1D)
#define SCRATCH_ELEMS (OFF_PART + PART_ELEMS)

__device__ float g_scratch[SCRATCH_ELEMS];

// fp16 weights (SAGE path) -- single-term
__device__ uint16_t g_w1h[(size_t)DHID * 1024];
__device__ uint16_t g_w2h[(size_t)1024 * DHID];
__device__ uint16_t g_wp1h[(size_t)P1D * 1024];
// split-bf16 weights (image path)
__device__ uint16_t g_wi1_hi[(size_t)768 * FEATD];
__device__ uint16_t g_wi1_lo[(size_t)768 * FEATD];
__device__ uint16_t g_wi2_hi[(size_t)1000 * 768];
__device__ uint16_t g_wi2_lo[(size_t)1000 * 768];
__device__ uint16_t g_wi3_hi[(size_t)EMBD * 1024];
__device__ uint16_t g_wi3_lo[(size_t)EMBD * 1024];
// fp16 buffers
__device__ uint16_t g_wp2h[(size_t)EMBD * P1D];
__device__ uint16_t g_ph[(size_t)NPAIRS * EMBD];
__device__ uint16_t g_pah[(size_t)NATTRS * P1D];
__device__ uint16_t g_poh[(size_t)NOBJS * P1D];

// ---------------- small kernels ----------------
__global__ void zero_kernel(float* p, int n) {
    int i = blockIdx.x * blockDim.x + threadIdx.x;
    if (i < n) p[i] = 0.0f;
}

__global__ void edge_count_kernel(const int* __restrict__ src,
                                  const int* __restrict__ dst,
                                  float* __restrict__ adj) {
    int e = blockIdx.x * blockDim.x + threadIdx.x;
    if (e < NEDGES) atomicAdd(&adj[(size_t)dst[e] * NNODES + src[e]], 1.0f);
}

__global__ void row_norm_kernel(float* __restrict__ adj) {
    __shared__ float sbuf[32];
    int r = blockIdx.x;
    int tid = threadIdx.x;
    float s = 0.0f;
    float* row = adj + (size_t)r * NNODES;
    for (int c = tid; c < NNODES; c += blockDim.x) s += row[c];
    for (int o = 16; o > 0; o >>= 1) s += __shfl_down_sync(0xffffffffu, s, o);
    if ((tid & 31) == 0) sbuf[tid >> 5] = s;
    __syncthreads();
    int nw = blockDim.x >> 5;
    if (tid < 32) {
        s = (tid < nw) ? sbuf[tid] : 0.0f;
        for (int o = 16; o > 0; o >>= 1) s += __shfl_down_sync(0xffffffffu, s, o);
        if (tid == 0) sbuf[0] = s;
    }
    __syncthreads();
    float inv = 1.0f / fmaxf(sbuf[0], 1.0f);
    for (int c = tid; c < NNODES; c += blockDim.x) row[c] *= inv;
}

// vectorized split-concat (x8) -> bf16 hi/lo
__global__ void splitcat8_kernel(const float* __restrict__ X1, int K1,
                                 const float* __restrict__ X2, int K2,
                                 uint16_t* __restrict__ hi, uint16_t* __restrict__ lo,
                                 int ldo, int Nrows) {
    int g = blockIdx.x * blockDim.x + threadIdx.x;
    int total = Nrows * ldo / 8;
    if (g >= total) return;
    int base = g * 8;
    int n = base / ldo, k = base - n * ldo;
    float v[8];
    if (k + 8 <= K1) {
        const float4* s = (const float4*)(X1 + (size_t)n * K1 + k);
        float4 a = s[0], b = s[1];
        v[0]=a.x; v[1]=a.y; v[2]=a.z; v[3]=a.w; v[4]=b.x; v[5]=b.y; v[6]=b.z; v[7]=b.w;
    } else if (k >= K1 && k + 8 <= K1 + K2) {
        const float4* s = (const float4*)(X2 + (size_t)n * K2 + (k - K1));
        float4 a = s[0], b = s[1];
        v[0]=a.x; v[1]=a.y; v[2]=a.z; v[3]=a.w; v[4]=b.x; v[5]=b.y; v[6]=b.z; v[7]=b.w;
    } else {
#pragma unroll
        for (int q = 0; q < 8; q++) {
            int kk = k + q;
            v[q] = (kk < K1) ? X1[(size_t)n * K1 + kk]
                 : (kk < K1 + K2 ? X2[(size_t)n * K2 + (kk - K1)] : 0.0f);
        }
    }
    union { uint16_t b[8]; uint4 u; } Uh, Ul;
#pragma unroll
    for (int q = 0; q < 8; q++) {
        __nv_bfloat16 h = __float2bfloat16(v[q]);
        Uh.b[q] = __bfloat16_as_ushort(h);
        Ul.b[q] = __bfloat16_as_ushort(__float2bfloat16(v[q] - __bfloat162float(h)));
    }
    *(uint4*)(hi + base) = Uh.u;
    *(uint4*)(lo + base) = Ul.u;
}

// vectorized split-concat (x8) -> single fp16
__global__ void splitcat8h_kernel(const float* __restrict__ X1, int K1,
                                  const float* __restrict__ X2, int K2,
                                  uint16_t* __restrict__ out,
                                  int ldo, int Nrows) {
    int g = blockIdx.x * blockDim.x + threadIdx.x;
    int total = Nrows * ldo / 8;
    if (g >= total) return;
    int base = g * 8;
    int n = base / ldo, k = base - n * ldo;
    float v[8];
    if (k + 8 <= K1) {
        const float4* s = (const float4*)(X1 + (size_t)n * K1 + k);
        float4 a = s[0], b = s[1];
        v[0]=a.x; v[1]=a.y; v[2]=a.z; v[3]=a.w; v[4]=b.x; v[5]=b.y; v[6]=b.z; v[7]=b.w;
    } else if (k >= K1 && k + 8 <= K1 + K2) {
        const float4* s = (const float4*)(X2 + (size_t)n * K2 + (k - K1));
        float4 a = s[0], b = s[1];
        v[0]=a.x; v[1]=a.y; v[2]=a.z; v[3]=a.w; v[4]=b.x; v[5]=b.y; v[6]=b.z; v[7]=b.w;
    } else {
#pragma unroll
        for (int q = 0; q < 8; q++) {
            int kk = k + q;
            v[q] = (kk < K1) ? X1[(size_t)n * K1 + kk]
                 : (kk < K1 + K2 ? X2[(size_t)n * K2 + (kk - K1)] : 0.0f);
        }
    }
    union { uint16_t b[8]; uint4 u; } U;
#pragma unroll
    for (int q = 0; q < 8; q++) U.b[q] = __half_as_ushort(__float2half_rn(v[q]));
    *(uint4*)(out + base) = U.u;
}

__global__ void tohalf8_kernel(const float* __restrict__ x,
                               uint16_t* __restrict__ y, int n8) {
    int g = blockIdx.x * blockDim.x + threadIdx.x;
    if (g >= n8) return;
    const float4* s = (const float4*)(x + g * 8);
    float4 a = s[0], b = s[1];
    union { uint16_t h[8]; uint4 u; } U;
    U.h[0] = __half_as_ushort(__float2half_rn(a.x));
    U.h[1] = __half_as_ushort(__float2half_rn(a.y));
    U.h[2] = __half_as_ushort(__float2half_rn(a.z));
    U.h[3] = __half_as_ushort(__float2half_rn(a.w));
    U.h[4] = __half_as_ushort(__float2half_rn(b.x));
    U.h[5] = __half_as_ushort(__float2half_rn(b.y));
    U.h[6] = __half_as_ushort(__float2half_rn(b.z));
    U.h[7] = __half_as_ushort(__float2half_rn(b.w));
    *(uint4*)(y + g * 8) = U.u;
}

// PP [650x1200] -> fp16 tables (x4 vectorized)
__global__ void pp2half4_kernel(const float* __restrict__ PP,
                                const float* __restrict__ bp1,
                                uint16_t* __restrict__ pah,
                                uint16_t* __restrict__ poh) {
    int g = blockIdx.x * blockDim.x + threadIdx.x;
    if (g >= NNODES * P1D / 4) return;
    int base = g * 4;
    int r = base / P1D, k = base - r * P1D;
    float4 v = *(const float4*)(PP + base);
    uint16_t* dst;
    if (r < NATTRS) {
        float4 b = *(const float4*)(bp1 + k);
        v.x += b.x; v.y += b.y; v.z += b.z; v.w += b.w;
        dst = pah + (size_t)r * P1D + k;
    } else {
        dst = poh + (size_t)(r - NATTRS) * P1D + k;
    }
    __half2 h0 = __floats2half2_rn(v.x, v.y);
    __half2 h1 = __floats2half2_rn(v.z, v.w);
    *(uint32_t*)(dst)     = *(uint32_t*)&h0;
    *(uint32_t*)(dst + 2) = *(uint32_t*)&h1;
}

// vectorized in-place LayerNorm (fp32), one row per block
__global__ void ln_kernel(float* __restrict__ X,
                          const float* __restrict__ g,
                          const float* __restrict__ b, int D) {
    __shared__ float sA[32], sB[32];
    int r = blockIdx.x;
    int tid = threadIdx.x;
    float* x = X + (size_t)r * D;
    const int nv = D / 4;
    float4 v = make_float4(0.f, 0.f, 0.f, 0.f);
    float s = 0.0f, s2 = 0.0f;
    if (tid < nv) {
        v = ((const float4*)x)[tid];
        s = v.x + v.y + v.z + v.w;
        s2 = v.x * v.x + v.y * v.y + v.z * v.z + v.w * v.w;
    }
    for (int o = 16; o > 0; o >>= 1) {
        s += __shfl_down_sync(0xffffffffu, s, o);
        s2 += __shfl_down_sync(0xffffffffu, s2, o);
    }
    if ((tid & 31) == 0) { sA[tid >> 5] = s; sB[tid >> 5] = s2; }
    __syncthreads();
    int nw = blockDim.x >> 5;
    if (tid < 32) {
        s = (tid < nw) ? sA[tid] : 0.0f;
        s2 = (tid < nw) ? sB[tid] : 0.0f;
        for (int o = 16; o > 0; o >>= 1) {
            s += __shfl_down_sync(0xffffffffu, s, o);
            s2 += __shfl_down_sync(0xffffffffu, s2, o);
        }
        if (tid == 0) { sA[0] = s; sB[0] = s2; }
    }
    __syncthreads();
    float invD = 1.0f / (float)D;
    float m = sA[0] * invD;
    float var = fmaxf(sB[0] * invD - m * m, 0.0f);
    float inv = rsqrtf(var + LNEPS);
    if (tid < nv) {
        float4 gg = ((const float4*)g)[tid];
        float4 bb = ((const float4*)b)[tid];
        float4 o;
        o.x = (v.x - m) * inv * gg.x + bb.x;
        o.y = (v.y - m) * inv * gg.y + bb.y;
        o.z = (v.z - m) * inv * gg.z + bb.z;
        o.w = (v.w - m) * inv * gg.w + bb.w;
        ((float4*)x)[tid] = o;
    }
}

// vectorized LayerNorm of Q rows -> fp16 P (EMBD=800)
__global__ void ln_half_kernel(const float* __restrict__ Q,
                               const float* __restrict__ g,
                               const float* __restrict__ b,
                               uint16_t* __restrict__ Ph) {
    __shared__ float sA[32], sB[32];
    int r = blockIdx.x;
    int tid = threadIdx.x;
    const float* x = Q + (size_t)r * EMBD;
    const int nv = EMBD / 4;
    float4 v = make_float4(0.f, 0.f, 0.f, 0.f);
    float s = 0.0f, s2 = 0.0f;
    if (tid < nv) {
        v = ((const float4*)x)[tid];
        s = v.x + v.y + v.z + v.w;
        s2 = v.x * v.x + v.y * v.y + v.z * v.z + v.w * v.w;
    }
    for (int o = 16; o > 0; o >>= 1) {
        s += __shfl_down_sync(0xffffffffu, s, o);
        s2 += __shfl_down_sync(0xffffffffu, s2, o);
    }
    if ((tid & 31) == 0) { sA[tid >> 5] = s; sB[tid >> 5] = s2; }
    __syncthreads();
    int nw = blockDim.x >> 5;
    if (tid < 32) {
        s = (tid < nw) ? sA[tid] : 0.0f;
        s2 = (tid < nw) ? sB[tid] : 0.0f;
        for (int o = 16; o > 0; o >>= 1) {
            s += __shfl_down_sync(0xffffffffu, s, o);
            s2 += __shfl_down_sync(0xffffffffu, s2, o);
        }
        if (tid == 0) { sA[0] = s; sB[0] = s2; }
    }
    __syncthreads();
    float invD = 1.0f / (float)EMBD;
    float m = sA[0] * invD;
    float var = fmaxf(sB[0] * invD - m * m, 0.0f);
    float inv = rsqrtf(var + LNEPS);
    if (tid < nv) {
        float4 gg = ((const float4*)g)[tid];
        float4 bb = ((const float4*)b)[tid];
        float p0 = (v.x - m) * inv * gg.x + bb.x;
        float p1 = (v.y - m) * inv * gg.y + bb.y;
        float p2 = (v.z - m) * inv * gg.z + bb.z;
        float p3 = (v.w - m) * inv * gg.w + bb.w;
        __half2 h0 = __floats2half2_rn(p0, p1);
        __half2 h1 = __floats2half2_rn(p2, p3);
        uint16_t* dst = Ph + (size_t)r * EMBD + tid * 4;
        *(uint32_t*)(dst)     = *(uint32_t*)&h0;
        *(uint32_t*)(dst + 2) = *(uint32_t*)&h1;
    }
}

// sum split-K partials + bias (+relu) -> C
__global__ void reduce_parts_kernel(const float* __restrict__ part, size_t pstride,
                                    int nz, const float* __restrict__ bias, int relu,
                                    float* __restrict__ C, int ldc, int ldp,
                                    int M, int NB) {
    int i = blockIdx.x * blockDim.x + threadIdx.x;
    if (i >= M * NB) return;
    int m = i / NB, n = i - m * NB;
    float s = 0.0f;
    for (int z = 0; z < nz; z++)
        s += part[(size_t)z * pstride + (size_t)m * ldp + n];
    if (bias) s += bias[n];
    if (relu) s = fmaxf(s, 0.0f);
    C[(size_t)m * ldc + n] = s;
}

// ---------------- small fp32 NN gemm (64x64 tiles) ----------------
__global__ __launch_bounds__(256)
void nn_small_kernel(const float* __restrict__ A, int lda,
                     const float* __restrict__ B, int ldb,
                     const float* __restrict__ bias,
                     const float* __restrict__ extra, int lde,
                     float* __restrict__ C, int ldc,
                     int M, int N, int K) {
    __shared__ float As[16][68];
    __shared__ float Bs[16][68];
    int tid = threadIdx.x;
    int bm = blockIdx.y * 64, bn = blockIdx.x * 64;
    int tx = tid & 15, ty = tid >> 4;
    float acc[4][4];
#pragma unroll
    for (int i = 0; i < 4; i++)
#pragma unroll
        for (int j = 0; j < 4; j++) acc[i][j] = 0.0f;
    for (int k0 = 0; k0 < K; k0 += 16) {
        for (int e = tid; e < 1024; e += 256) {
            int row = e & 63, kk = e >> 6;
            int gm = bm + row, gk = k0 + kk, gn = bn + row;
            As[kk][row] = (gm < M && gk < K) ? A[(size_t)gm * lda + gk] : 0.0f;
            Bs[kk][row] = (gn < N && gk < K) ? B[(size_t)gk * ldb + gn] : 0.0f;
        }
        __syncthreads();
#pragma unroll
        for (int kk = 0; kk < 16; kk++) {
            float a[4], b[4];
#pragma unroll
            for (int i = 0; i < 4; i++) a[i] = As[kk][ty * 4 + i];
#pragma unroll
            for (int j = 0; j < 4; j++) b[j] = Bs[kk][tx * 4 + j];
#pragma unroll
            for (int i = 0; i < 4; i++)
#pragma unroll
                for (int j = 0; j < 4; j++) acc[i][j] += a[i] * b[j];
        }
        __syncthreads();
    }
#pragma unroll
    for (int i = 0; i < 4; i++) {
        int m = bm + ty * 4 + i;
        if (m >= M) continue;
#pragma unroll
        for (int j = 0; j < 4; j++) {
            int n = bn + tx * 4 + j;
            if (n >= N) continue;
            float v = acc[i][j];
            if (bias) v += bias[n];
            if (extra) v += extra[(size_t)m * lde + n];
            C[(size_t)m * ldc + n] = v;
        }
    }
}

// ================= generalized tensor-core GEMM =================
__device__ __forceinline__ uint32_t smem_u32(const void* p) {
    return (uint32_t)__cvta_generic_to_shared(p);
}
__device__ __forceinline__ void ldmA4(uint32_t r[4], uint32_t addr) {
    asm volatile("ldmatrix.sync.aligned.m8n8.x4.shared.b16 {%0,%1,%2,%3},[%4];\n"
                 : "=r"(r[0]), "=r"(r[1]), "=r"(r[2]), "=r"(r[3]) : "r"(addr));
}
__device__ __forceinline__ void ldmB2(uint32_t r[2], uint32_t addr) {
    asm volatile("ldmatrix.sync.aligned.m8n8.x2.shared.b16 {%0,%1},[%2];\n"
                 : "=r"(r[0]), "=r"(r[1]) : "r"(addr));
}
__device__ __forceinline__ void ldmB4(uint32_t r0[2], uint32_t r1[2], uint32_t addr) {
    asm volatile("ldmatrix.sync.aligned.m8n8.x4.shared.b16 {%0,%1,%2,%3},[%4];\n"
                 : "=r"(r0[0]), "=r"(r0[1]), "=r"(r1[0]), "=r"(r1[1]) : "r"(addr));
}
__device__ __forceinline__ void mma_f16(float d[4], const uint32_t a[4],
                                        const uint32_t b[2]) {
    asm volatile(
        "mma.sync.aligned.m16n8k16.row.col.f32.f16.f16.f32 "
        "{%0,%1,%2,%3},{%4,%5,%6,%7},{%8,%9},{%0,%1,%2,%3};\n"
        : "+f"(d[0]), "+f"(d[1]), "+f"(d[2]), "+f"(d[3])
        : "r"(a[0]), "r"(a[1]), "r"(a[2]), "r"(a[3]), "r"(b[0]), "r"(b[1]));
}
__device__ __forceinline__ void mma_bf16(float d[4], const uint32_t a[4],
                                         const uint32_t b[2]) {
    asm volatile(
        "mma.sync.aligned.m16n8k16.row.col.f32.bf16.bf16.f32 "
        "{%0,%1,%2,%3},{%4,%5,%6,%7},{%8,%9},{%0,%1,%2,%3};\n"
        : "+f"(d[0]), "+f"(d[1]), "+f"(d[2]), "+f"(d[3])
        : "r"(a[0]), "r"(a[1]), "r"(a[2]), "r"(a[3]), "r"(b[0]), "r"(b[1]));
}
__device__ __forceinline__ void cp16(uint32_t dst, const void* src) {
    asm volatile("cp.async.cg.shared.global [%0], [%1], 16;\n" :: "r"(dst), "l"(src));
}
__device__ __forceinline__ void cp_commit() { asm volatile("cp.async.commit_group;\n"); }
__device__ __forceinline__ void cp_wait0()  { asm volatile("cp.async.wait_group 0;\n"); }

__device__ __forceinline__ uint32_t h2addrelu(uint32_t a, uint32_t b) {
    __half2 ha = *(__half2*)&a;
    __half2 hb = *(__half2*)&b;
    __half2 r = __hmax2(__hadd2(ha, hb), __float2half2_rn(0.0f));
    return *(uint32_t*)&r;
}
__device__ __forceinline__ uint4 h2addrelu4(uint4 a, uint4 b) {
    uint4 r;
    r.x = h2addrelu(a.x, b.x); r.y = h2addrelu(a.y, b.y);
    r.z = h2addrelu(a.z, b.z); r.w = h2addrelu(a.w, b.w);
    return r;
}

template <int AMODE, int SPLIT, int RELU, int NT_, int KS_>
__global__ __launch_bounds__(256)
void mma2_kernel(const float* __restrict__ A1, int lda1,
                 const float* __restrict__ A2, int lda2, int K1,
                 const uint16_t* __restrict__ H1,
                 const uint16_t* __restrict__ H2, int ldh,
                 const uint16_t* __restrict__ Bhi,
                 const uint16_t* __restrict__ Blo, int ldb,
                 float* __restrict__ C, int ldc,
                 int M, int NB, int K,
                 const float* __restrict__ bias,
                 int kchunk, size_t pstride) {
    constexpr int NI   = NT_ / 32;
    constexpr int RB   = (KS_ + 8) * 2;
    constexpr int ASZ  = 128 * RB;
    constexpr int BSZ  = NT_ * RB;
    constexpr int NPLA = SPLIT ? 2 : 1;
    constexpr int STRIDE = NPLA * (ASZ + BSZ);
    constexpr int AhiO = 0;
    constexpr int AloO = ASZ;
    constexpr int BhiO = NPLA * ASZ;
    constexpr int BloO = NPLA * ASZ + BSZ;
    constexpr int NSUB = KS_ / 16;
    constexpr int GH   = KS_ / 16;

    extern __shared__ char smem[];
    const uint32_t sb = smem_u32(smem);
    const int tid = threadIdx.x;
    const int warp = tid >> 5;
    const int lane = tid & 31;
    const int bm = blockIdx.y * 128;
    const int bn = blockIdx.x * NT_;
    const int wm = warp & 1;
    const int wn = warp >> 1;

    int koff = 0, kend = K;
    if (kchunk > 0) {
        koff = blockIdx.z * kchunk;
        int ke = koff + kchunk;
        kend = ke < K ? ke : K;
        C += (size_t)blockIdx.z * pstride;
    }

    const int ar = tid >> 1;
    const int ah = (tid & 1) * (KS_ / 2);
    const int arow = bm + ar;
    const bool avalid = arow < M;
    const float* pA = nullptr;
    const float* pA2 = nullptr;
    const uint16_t* pH1 = nullptr;
    const uint16_t* pH2 = nullptr;
    bool attr_row = true;
    if (AMODE == 0) {
        pA = A1 + (size_t)(avalid ? arow : 0) * lda1;
    } else if (AMODE == 1) {
        int ai = avalid ? (arow / NOBJS) : 0;
        int oi = avalid ? (arow - ai * NOBJS) : 0;
        pH1 = H1 + (size_t)ai * ldh;
        pH2 = H2 + (size_t)oi * ldh;
    } else if (AMODE == 2) {
        pA = A1 + (size_t)(avalid ? arow : 0) * lda1;
        pA2 = A2 + (size_t)(avalid ? arow : 0) * lda2;
    } else {
        pA = A1 + (size_t)(avalid ? arow : 0) * lda1;
        attr_row = arow < NATTRS;
    }

    float acc[4][NI][4];
#pragma unroll
    for (int i = 0; i < 4; i++)
#pragma unroll
        for (int j = 0; j < NI; j++)
#pragma unroll
            for (int c = 0; c < 4; c++) acc[i][j][c] = 0.0f;

    float va[KS_ / 2];
    uint4 vh[GH];
    auto load_A = [&](int kb) {
        int k0 = kb + ah;
        if (AMODE == 1) {
#pragma unroll
            for (int g = 0; g < GH; g++) {
                int kg = k0 + g * 8;
                if (avalid && kg < kend) {
                    vh[g] = h2addrelu4(*(const uint4*)(pH1 + kg),
                                       *(const uint4*)(pH2 + kg));
                } else {
                    vh[g] = make_uint4(0, 0, 0, 0);
                }
            }
            return;
        }
#pragma unroll
        for (int q = 0; q < KS_ / 2; q++) va[q] = 0.0f;
#pragma unroll
        for (int g = 0; g < KS_ / 8; g++) {
            int kg = k0 + g * 4;
            if (!avalid || kg >= kend) continue;
            const float* src = nullptr;
            if (AMODE == 0) {
                src = pA + kg;
            } else if (AMODE == 2) {
                src = (kg < K1) ? (pA + kg) : (pA2 + (kg - K1));
            } else {
                bool use = attr_row ? (kg < K1) : (kg >= K1);
                if (!use) continue;
                src = attr_row ? (pA + kg) : (pA + (kg - K1));
            }
            float4 x = *(const float4*)(src);
            va[g*4+0] = x.x; va[g*4+1] = x.y; va[g*4+2] = x.z; va[g*4+3] = x.w;
        }
    };
    auto sts_A = [&](int buf) {
        const int base = buf * STRIDE;
        uint32_t off = (uint32_t)(ar * RB + ah * 2);
        if (AMODE == 1) {
#pragma unroll
            for (int g = 0; g < GH; g++)
                *(uint4*)(smem + base + AhiO + off + g * 16) = vh[g];
            return;
        }
#pragma unroll
        for (int g = 0; g < GH; g++) {
            union { uint16_t b[8]; uint4 u; } Uh, Ul;
#pragma unroll
            for (int q = 0; q < 8; q++) {
                float v = va[g * 8 + q];
                if (SPLIT) {
                    __nv_bfloat16 h = __float2bfloat16(v);
                    Uh.b[q] = __bfloat16_as_ushort(h);
                    Ul.b[q] = __bfloat16_as_ushort(__float2bfloat16(v - __bfloat162float(h)));
                } else {
                    Uh.b[q] = __half_as_ushort(__float2half_rn(v));
                }
            }
            *(uint4*)(smem + base + AhiO + off + g * 16) = Uh.u;
            if (SPLIT) *(uint4*)(smem + base + AloO + off + g * 16) = Ul.u;
        }
    };
    auto load_B = [&](int kb, int buf) {
        const int base = buf * STRIDE;
        constexpr int CPR = KS_ / 8;
        const int total = NT_ * CPR * NPLA;
        for (int i = tid; i < total; i += 256) {
            int plane = (i >= NT_ * CPR) ? 1 : 0;
            int v = i - plane * NT_ * CPR;
            int row = v / CPR;
            int c = v - row * CPR;
            int k0 = kb + c * 8;
            uint32_t doff = (uint32_t)(base + (plane ? BloO : BhiO) + row * RB + c * 16);
            if ((bn + row) < NB && k0 < kend) {
                const uint16_t* src = (plane ? Blo : Bhi) + (size_t)(bn + row) * ldb + k0;
                cp16(sb + doff, src);
            } else {
                *(uint4*)(smem + doff) = make_uint4(0u, 0u, 0u, 0u);
            }
        }
    };

    const int NST = (kend - koff + KS_ - 1) / KS_;
    load_A(koff);
    sts_A(0);
    load_B(koff, 0);
    cp_commit();
    cp_wait0();
    __syncthreads();

    const int arowf = lane & 15;
    const int akf = ((lane >> 4) & 1) * 8;
    const int brow = lane & 7;
    const int bkf = ((lane >> 3) & 1) * 8;
    const int browx = (lane & 7) + ((lane & 16) >> 1);
    const int bkx = (lane & 8);

    for (int st = 0; st < NST; st++) {
        const int cur = st & 1;
        const int nxt = cur ^ 1;
        const bool hasnext = (st + 1) < NST;
        if (hasnext) {
            load_A(koff + (st + 1) * KS_);
            load_B(koff + (st + 1) * KS_, nxt);
            cp_commit();
        }
        const int cbase = cur * STRIDE;
#pragma unroll
        for (int sub = 0; sub < NSUB; sub++) {
            if (koff + st * KS_ + sub * 16 >= kend) break;
            const int kcol = (sub * 16 + akf) * 2;
            const int kcolb = (sub * 16 + bkf) * 2;
            const int kcolx = (sub * 16 + bkx) * 2;
            uint32_t afh[4][4], afl[4][4];
#pragma unroll
            for (int mi = 0; mi < 4; mi++) {
                int m0 = wm * 64 + mi * 16;
                ldmA4(afh[mi], sb + cbase + AhiO + (m0 + arowf) * RB + kcol);
                if (SPLIT)
                    ldmA4(afl[mi], sb + cbase + AloO + (m0 + arowf) * RB + kcol);
            }
            uint32_t bfh[NI][2], bfl[NI][2];
#pragma unroll
            for (int ni = 0; ni + 1 < NI; ni += 2) {
                int n0 = wn * (NT_ / 4) + ni * 8;
                ldmB4(bfh[ni], bfh[ni + 1],
                      sb + cbase + BhiO + (n0 + browx) * RB + kcolx);
                if (SPLIT)
                    ldmB4(bfl[ni], bfl[ni + 1],
                          sb + cbase + BloO + (n0 + browx) * RB + kcolx);
            }
            if (NI & 1) {
                constexpr int ni = NI - 1;
                int n0 = wn * (NT_ / 4) + ni * 8;
                ldmB2(bfh[ni], sb + cbase + BhiO + (n0 + brow) * RB + kcolb);
                if (SPLIT)
                    ldmB2(bfl[ni], sb + cbase + BloO + (n0 + brow) * RB + kcolb);
            }
#pragma unroll
            for (int mi = 0; mi < 4; mi++)
#pragma unroll
                for (int ni = 0; ni < NI; ni++) {
                    if (SPLIT) {
                        mma_bf16(acc[mi][ni], afh[mi], bfh[ni]);
                        mma_bf16(acc[mi][ni], afh[mi], bfl[ni]);
                        mma_bf16(acc[mi][ni], afl[mi], bfh[ni]);
                    } else {
                        mma_f16(acc[mi][ni], afh[mi], bfh[ni]);
                    }
                }
        }
        if (hasnext) sts_A(nxt);
        cp_wait0();
        __syncthreads();
    }

    // epilogue
#pragma unroll
    for (int mi = 0; mi < 4; mi++) {
#pragma unroll
        for (int ni = 0; ni < NI; ni++) {
            int m0 = bm + wm * 64 + mi * 16 + (lane >> 2);
            int n0 = bn + wn * (NT_ / 4) + ni * 8 + (lane & 3) * 2;
            if (n0 >= NB) continue;
            float b0 = bias ? bias[n0] : 0.0f;
            float b1v = bias ? bias[n0 + 1] : 0.0f;
            float v0 = acc[mi][ni][0] + b0, v1 = acc[mi][ni][1] + b1v;
            float v2 = acc[mi][ni][2] + b0, v3 = acc[mi][ni][3] + b1v;
            if (RELU) {
                v0 = fmaxf(v0, 0.0f); v1 = fmaxf(v1, 0.0f);
                v2 = fmaxf(v2, 0.0f); v3 = fmaxf(v3, 0.0f);
            }
            if (m0 < M) *(float2*)(C + (size_t)m0 * ldc + n0) = make_float2(v0, v1);
            if (m0 + 8 < M) *(float2*)(C + (size_t)(m0 + 8) * ldc + n0) = make_float2(v2, v3);
        }
    }
}

// ---------------- host ----------------
static inline int ceildiv(int a, int b) { return (a + b - 1) / b; }

extern "C" void kernel_launch(void* const* d_in, const int* in_sizes, int n_in,
                              void* d_out, int out_size) {
    const float* img   = (const float*)d_in[0];
    const float* nodes = (const float*)d_in[1];
    const int*   esrc  = (const int*)d_in[2];
    const int*   edst  = (const int*)d_in[3];
    const float* W1l   = (const float*)d_in[4];
    const float* b1    = (const float*)d_in[5];
    const float* W1r   = (const float*)d_in[6];
    const float* W2l   = (const float*)d_in[7];
    const float* b2    = (const float*)d_in[8];
    const float* W2r   = (const float*)d_in[9];
    const float* Wp1   = (const float*)d_in[10];
    const float* bp1   = (const float*)d_in[11];
    const float* Wp2   = (const float*)d_in[12];
    const float* bp2   = (const float*)d_in[13];
    const float* gp    = (const float*)d_in[14];
    const float* bpn   = (const float*)d_in[15];
    const float* Wi1   = (const float*)d_in[16];
    const float* bi1   = (const float*)d_in[17];
    const float* Wi2   = (const float*)d_in[18];
    const float* bi2   = (const float*)d_in[19];
    const float* Wi3   = (const float*)d_in[20];
    const float* bi3   = (const float*)d_in[21];
    const float* gi    = (const float*)d_in[22];
    const float* bin_  = (const float*)d_in[23];
    float* out = (float*)d_out;

    void* p;
    cudaGetSymbolAddress(&p, g_scratch);
    float* S0 = (float*)p;
    uint16_t *w1h, *w2h, *wp1h, *wi1h, *wi1l, *wi2h, *wi2l, *wi3h, *wi3l,
             *wp2h, *Ph, *pah, *poh;
    cudaGetSymbolAddress(&p, g_w1h);    w1h  = (uint16_t*)p;
    cudaGetSymbolAddress(&p, g_w2h);    w2h  = (uint16_t*)p;
    cudaGetSymbolAddress(&p, g_wp1h);   wp1h = (uint16_t*)p;
    cudaGetSymbolAddress(&p, g_wi1_hi); wi1h = (uint16_t*)p;
    cudaGetSymbolAddress(&p, g_wi1_lo); wi1l = (uint16_t*)p;
    cudaGetSymbolAddress(&p, g_wi2_hi); wi2h = (uint16_t*)p;
    cudaGetSymbolAddress(&p, g_wi2_lo); wi2l = (uint16_t*)p;
    cudaGetSymbolAddress(&p, g_wi3_hi); wi3h = (uint16_t*)p;
    cudaGetSymbolAddress(&p, g_wi3_lo); wi3l = (uint16_t*)p;
    cudaGetSymbolAddress(&p, g_wp2h);   wp2h = (uint16_t*)p;
    cudaGetSymbolAddress(&p, g_ph);     Ph   = (uint16_t*)p;
    cudaGetSymbolAddress(&p, g_pah);    pah  = (uint16_t*)p;
    cudaGetSymbolAddress(&p, g_poh);    poh  = (uint16_t*)p;

    float* adj   = S0 + OFF_ADJ;
    float* mean1 = S0 + OFF_MEAN1;
    float* h     = S0 + OFF_H;
    float* T2    = S0 + OFF_T2;
    float* on    = S0 + OFF_ON;
    float* PP    = S0 + OFF_PP;
    float* Q     = S0 + OFF_Q;
    float* i1    = S0 + OFF_I1;
    float* i2    = S0 + OFF_I2;
    float* i3    = S0 + OFF_I3;
    float* part  = S0 + OFF_PART;

    const int SM_S128 = 2 * (2 * (128 * 80) + 2 * (128 * 80));   // split-bf16 NT=128
    const int SM_S160 = 2 * (2 * (128 * 80) + 2 * (160 * 80));   // split-bf16 NT=160
    const int SM_F128 = 2 * ((128 * 80) + (128 * 80));           // fp16 NT=128
    const int SM_F160 = 2 * ((128 * 80) + (160 * 80));           // fp16 NT=160
    cudaFuncSetAttribute(mma2_kernel<2,0,1,128,32>, cudaFuncAttributeMaxDynamicSharedMemorySize, SM_F128);
    cudaFuncSetAttribute(mma2_kernel<0,0,0,128,32>, cudaFuncAttributeMaxDynamicSharedMemorySize, SM_F128);
    cudaFuncSetAttribute(mma2_kernel<3,0,0,160,32>, cudaFuncAttributeMaxDynamicSharedMemorySize, SM_F160);
    cudaFuncSetAttribute(mma2_kernel<0,1,0,128,32>, cudaFuncAttributeMaxDynamicSharedMemorySize, SM_S128);
    cudaFuncSetAttribute(mma2_kernel<0,1,0,160,32>, cudaFuncAttributeMaxDynamicSharedMemorySize, SM_S160);
    cudaFuncSetAttribute(mma2_kernel<1,0,0,160,32>, cudaFuncAttributeMaxDynamicSharedMemorySize, SM_F160);
    cudaFuncSetAttribute(mma2_kernel<0,0,0,160,32>, cudaFuncAttributeMaxDynamicSharedMemorySize, SM_F160);

    // ---- graph: dense normalized adjacency ----
    {
        int n = NNODES * NNODES;
        zero_kernel<<<(n + 255) / 256, 256>>>(adj, n);
        edge_count_kernel<<<(NEDGES + 255) / 256, 256>>>(esrc, edst, adj);
        row_norm_kernel<<<NNODES, 256>>>(adj);
    }

    // ---- weight prep ----
    {
        int n8;
        // SAGE weights -> fp16 single
        n8 = DHID * 1024 / 8;
        splitcat8h_kernel<<<(n8 + 255) / 256, 256>>>(W1l, DIN, W1r, DIN, w1h, 1024, DHID);
        n8 = 512 * DHID / 8;
        splitcat8h_kernel<<<(n8 + 255) / 256, 256>>>(W2l, DHID, nullptr, 0, w2h, DHID, 512);
        splitcat8h_kernel<<<(n8 + 255) / 256, 256>>>(W2r, DHID, nullptr, 0,
                                                     w2h + (size_t)512 * DHID, DHID, 512);
        n8 = P1D * 1024 / 8;
        splitcat8h_kernel<<<(n8 + 255) / 256, 256>>>(Wp1, 1024, nullptr, 0, wp1h, 1024, P1D);
        // image weights -> split-bf16
        n8 = 768 * FEATD / 8;
        splitcat8_kernel<<<(n8 + 255) / 256, 256>>>(Wi1, FEATD, nullptr, 0, wi1h, wi1l, FEATD, 768);
        n8 = 1000 * 768 / 8;
        splitcat8_kernel<<<(n8 + 255) / 256, 256>>>(Wi2, 768, nullptr, 0, wi2h, wi2l, 768, 1000);
        n8 = EMBD * 1024 / 8;
        splitcat8_kernel<<<(n8 + 255) / 256, 256>>>(Wi3, 1000, nullptr, 0, wi3h, wi3l, 1024, EMBD);
        n8 = EMBD * P1D / 8;
        tohalf8_kernel<<<(n8 + 255) / 256, 256>>>(Wp2, wp2h, n8);
    }

    // ---- mean1 = adj @ nodes  (fp32 SIMT) ----
    nn_small_kernel<<<dim3(DIN / 64, ceildiv(NNODES, 64)), 256>>>(
        adj, NNODES, nodes, DIN, nullptr, nullptr, 0, mean1, DIN, NNODES, DIN, NNODES);

    // ---- h = relu([mean1|nodes] @ [W1l|W1r]^T + b1)  (fp16) ----
    mma2_kernel<2,0,1,128,32><<<dim3(DHID / 128, ceildiv(NNODES, 128)), 256, SM_F128>>>(
        mean1, DIN, nodes, DIN, DIN, nullptr, nullptr, 0,
        w1h, nullptr, 1024, h, DHID, NNODES, DHID, 1024, b1, 0, 0);

    // ---- T2 = h @ [W2l;W2r]^T  (fp16, split-K 4) ----
    {
        size_t ps = (size_t)NNODES * 1024;
        mma2_kernel<0,0,0,128,32><<<dim3(1024 / 128, ceildiv(NNODES, 128), 4), 256, SM_F128>>>(
            h, DHID, nullptr, 0, 0, nullptr, nullptr, 0,
            w2h, nullptr, DHID, part, 1024, NNODES, 1024, DHID, nullptr, 1024, ps);
        int n = NNODES * 1024;
        reduce_parts_kernel<<<(n + 255) / 256, 256>>>(part, ps, 4, nullptr, 0,
                                                      T2, 1024, 1024, NNODES, 1024);
    }

    // ---- on = adj @ T2[:, :512] + b2 + T2[:, 512:]  (fp32 SIMT) ----
    nn_small_kernel<<<dim3(DNODE / 64, ceildiv(NNODES, 64)), 256>>>(
        adj, NNODES, T2, 1024, b2, T2 + 512, 1024, on, DNODE, NNODES, DNODE, NNODES);

    // ---- PP = blockdiag(on) @ Wp1^T  (fp16, split-K 4) ----
    {
        size_t ps = (size_t)NNODES * P1D;
        mma2_kernel<3,0,0,160,32><<<dim3(ceildiv(P1D, 160), ceildiv(NNODES, 128), 4), 256, SM_F160>>>(
            on, DNODE, nullptr, 0, DNODE, nullptr, nullptr, 0,
            wp1h, nullptr, 1024, part, P1D, NNODES, P1D, 1024, nullptr, 256, ps);
        int n = NNODES * P1D;
        reduce_parts_kernel<<<(n + 255) / 256, 256>>>(part, ps, 4, nullptr, 0,
                                                      PP, P1D, P1D, NNODES, P1D);
    }

    // ---- PP -> fp16 tables ----
    {
        int n4 = NNODES * P1D / 4;
        pp2half4_kernel<<<(n4 + 255) / 256, 256>>>(PP, bp1, pah, poh);
    }

    // ---- Q = relu16(pah_i + poh_j) @ Wp2^T + bp2  (fp16) ----
    mma2_kernel<1,0,0,160,32><<<dim3(EMBD / 160, ceildiv(NPAIRS, 128)), 256, SM_F160>>>(
        nullptr, 0, nullptr, 0, 0, pah, poh, P1D,
        wp2h, nullptr, P1D, Q, EMBD, NPAIRS, EMBD, P1D, bp2, 0, 0);

    // ---- LN rows of Q -> fp16 P ----
    ln_half_kernel<<<NPAIRS, 256>>>(Q, gp, bpn, Ph);

    // ---- image MLP (split-bf16, split-K) ----
    {
        size_t ps = (size_t)BATCH * 768;
        mma2_kernel<0,1,0,128,32><<<dim3(768 / 128, ceildiv(BATCH, 128), 8), 256, SM_S128>>>(
            img, FEATD, nullptr, 0, 0, nullptr, nullptr, 0,
            wi1h, wi1l, FEATD, part, 768, BATCH, 768, FEATD, nullptr, 256, ps);
        int n = BATCH * 768;
        reduce_parts_kernel<<<(n + 255) / 256, 256>>>(part, ps, 8, bi1, 1,
                                                      i1, 768, 768, BATCH, 768);
    }
    zero_kernel<<<(BATCH * 1024 + 255) / 256, 256>>>(i2, BATCH * 1024);
    {
        size_t ps = (size_t)BATCH * 1024;
        mma2_kernel<0,1,0,128,32><<<dim3(ceildiv(1000, 128), ceildiv(BATCH, 128), 4), 256, SM_S128>>>(
            i1, 768, nullptr, 0, 0, nullptr, nullptr, 0,
            wi2h, wi2l, 768, part, 1024, BATCH, 1000, 768, nullptr, 192, ps);
        int n = BATCH * 1000;
        reduce_parts_kernel<<<(n + 255) / 256, 256>>>(part, ps, 4, bi2, 1,
                                                      i2, 1024, 1024, BATCH, 1000);
    }
    {
        size_t ps = (size_t)BATCH * EMBD;
        mma2_kernel<0,1,0,160,32><<<dim3(EMBD / 160, ceildiv(BATCH, 128), 8), 256, SM_S160>>>(
            i2, 1024, nullptr, 0, 0, nullptr, nullptr, 0,
            wi3h, wi3l, 1024, part, EMBD, BATCH, EMBD, 1024, nullptr, 128, ps);
        int n = BATCH * EMBD;
        reduce_parts_kernel<<<(n + 255) / 256, 256>>>(part, ps, 8, bi3, 0,
                                                      i3, EMBD, EMBD, BATCH, EMBD);
    }
    ln_kernel<<<BATCH, 256>>>(i3, gi, bin_, EMBD);

    // ---- out = iLN @ P^T  (fp16)  [256 x 100000] ----
    mma2_kernel<0,0,0,160,32><<<dim3(NPAIRS / 160, ceildiv(BATCH, 128)), 256, SM_F160>>>(
        i3, EMBD, nullptr, 0, 0, nullptr, nullptr, 0,
        Ph, nullptr, EMBD, out, NPAIRS, BATCH, NPAIRS, EMBD, nullptr, 0, 0);
}